// round 12
// baseline (speedup 1.0000x reference)
#include <cuda_runtime.h>
#include <cstdint>

#define LQ 512
#define LLQ (512*512)
#define PAD 132    // activation stride (scalar frags conflict-free: 4g+t)
#define WSTR 136   // weight row-major stride (scalar B frags conflict-free: 8t+g)

// scratch. g_a and g_bt have the K dim (m) PERMUTED within 8-blocks:
// pos = (m&~7) | ((m&3)<<1) | ((m>>2)&1)
__device__ float g_a [(size_t)128 * LLQ];   // a [c][i][perm(m)] (tf32)
__device__ float g_bt[(size_t)128 * LLQ];   // b^T [c][j][perm(m)] (tf32)
__device__ float g_k [(size_t)128 * LLQ];   // k [c][i][j]       (fp32, plain)

__device__ __forceinline__ float sigmoidf_(float x) {
    return 1.0f / (1.0f + __expf(-x));
}
__device__ __forceinline__ float to_tf32(float x) {
    uint32_t u;
    asm("cvt.rna.tf32.f32 %0, %1;" : "=r"(u) : "f"(x));
    return __uint_as_float(u);
}
__device__ __forceinline__ uint32_t smem_u32(const void* p) {
    uint32_t a;
    asm("{ .reg .u64 t; cvta.to.shared.u64 t, %1; cvt.u32.u64 %0, t; }" : "=r"(a) : "l"(p));
    return a;
}
__device__ __forceinline__ void mma_tf32(float* d, uint32_t a0, uint32_t a1, uint32_t a2, uint32_t a3,
                                         uint32_t b0, uint32_t b1) {
    asm volatile(
        "mma.sync.aligned.m16n8k8.row.col.f32.tf32.tf32.f32 "
        "{%0,%1,%2,%3}, {%4,%5,%6,%7}, {%8,%9}, {%0,%1,%2,%3};"
        : "+f"(d[0]), "+f"(d[1]), "+f"(d[2]), "+f"(d[3])
        : "r"(a0), "r"(a1), "r"(a2), "r"(a3), "r"(b0), "r"(b1));
}

#define CP_ASYNC16(dst, src) \
    asm volatile("cp.async.ca.shared.global [%0], [%1], 16;" :: "r"(dst), "l"(src) : "memory")
#define CP_ASYNC4(dst, src) \
    asm volatile("cp.async.ca.shared.global [%0], [%1], 4;"  :: "r"(dst), "l"(src) : "memory")
#define CP_COMMIT() asm volatile("cp.async.commit_group;" ::: "memory")
#define CP_WAIT1()  asm volatile("cp.async.wait_group 1;"  ::: "memory")
#define CP_WAIT0()  asm volatile("cp.async.wait_group 0;"  ::: "memory")

// ---------------------------------------------------------------------------
// Kernel 1 (merged): LN(z) + gated projections for BOTH outputs.
// blockIdx.x < 2048: a-job (i-major tile -> g_a [c][i][perm(m)])
// blockIdx.x >= 2048: bt-job (fixed j, m-range -> g_bt [c][j][perm(m)])
// grid 4096, 512 thr = 16 warps (8m x 2n), warp tile 16x64.
// ---------------------------------------------------------------------------
__global__ void __launch_bounds__(512, 1) k_proj_merged(
    const float* __restrict__ z,
    const float* __restrict__ lnw, const float* __restrict__ lnb,
    const float* __restrict__ Wga, const float* __restrict__ bga,
    const float* __restrict__ Wla, const float* __restrict__ bla,
    const float* __restrict__ Wgb, const float* __restrict__ bgb,
    const float* __restrict__ Wlb, const float* __restrict__ blb)
{
    extern __shared__ float sm[];
    float* zn  = sm;                          // [128][PAD]
    float* Wt0 = sm + 128 * PAD;              // [128][WSTR]
    float* Wt1 = sm + 128 * PAD + 128 * WSTR; // [128][WSTR]

    const int tid  = threadIdx.x;
    const bool jobA = (blockIdx.x < 2048);
    const int bx   = jobA ? blockIdx.x : (blockIdx.x - 2048);
    const int lane = tid & 31, warp = tid >> 5;
    const uint32_t sW0 = smem_u32(Wt0);
    const uint32_t sW1 = smem_u32(Wt1);

    const float* Wg = jobA ? Wga : Wgb;
    const float* Wl = jobA ? Wla : Wlb;
    const float* bg = jobA ? bga : bgb;
    const float* bl = jobA ? bla : blb;

    #pragma unroll
    for (int it = 0; it < 8; ++it) {
        int idx = it * 512 + tid;
        int k = idx >> 5, q = idx & 31;
        uint32_t off = (uint32_t)(k * WSTR + q * 4) * 4u;
        CP_ASYNC16(sW0 + off, Wg + k * 128 + q * 4);
        CP_ASYNC16(sW1 + off, Wl + k * 128 + q * 4);
    }
    CP_COMMIT();

    // LN -> zn. jobA: rows r0+row contiguous; jobB: rows (m0+row)*512 + j
    {
        const int r0 = bx * 128;               // jobA
        const int m0 = (bx & 3) * 128;         // jobB
        const int j  = bx >> 2;                // jobB
        const float w0 = lnw[lane], w1 = lnw[lane + 32], w2 = lnw[lane + 64], w3 = lnw[lane + 96];
        const float c0 = lnb[lane], c1 = lnb[lane + 32], c2 = lnb[lane + 64], c3 = lnb[lane + 96];
        for (int it = 0; it < 8; ++it) {
            int row = warp * 8 + it;
            const float* zr = jobA ? (z + (size_t)(r0 + row) * 128)
                                   : (z + ((size_t)(m0 + row) * LQ + j) * 128);
            float x0 = zr[lane], x1 = zr[lane + 32], x2 = zr[lane + 64], x3 = zr[lane + 96];
            float s = x0 + x1 + x2 + x3;
            float q = x0 * x0 + x1 * x1 + x2 * x2 + x3 * x3;
            #pragma unroll
            for (int o = 16; o > 0; o >>= 1) {
                s += __shfl_xor_sync(0xffffffffu, s, o);
                q += __shfl_xor_sync(0xffffffffu, q, o);
            }
            float mu  = s * (1.0f / 128.0f);
            float var = q * (1.0f / 128.0f) - mu * mu;
            float rs  = rsqrtf(var + 1e-5f);
            float* zo = zn + row * PAD;
            zo[lane]      = to_tf32((x0 - mu) * rs * w0 + c0);
            zo[lane + 32] = to_tf32((x1 - mu) * rs * w1 + c1);
            zo[lane + 64] = to_tf32((x2 - mu) * rs * w2 + c2);
            zo[lane + 96] = to_tf32((x3 - mu) * rs * w3 + c3);
        }
    }

    CP_WAIT0();
    __syncthreads();
    #pragma unroll
    for (int it = 0; it < 8; ++it) {
        int idx = it * 512 + tid;
        int k = idx >> 5, q = idx & 31;
        float4* p0 = (float4*)(Wt0 + k * WSTR + q * 4);
        float4* p1 = (float4*)(Wt1 + k * WSTR + q * 4);
        float4 v0 = *p0, v1 = *p1;
        v0.x = to_tf32(v0.x); v0.y = to_tf32(v0.y); v0.z = to_tf32(v0.z); v0.w = to_tf32(v0.w);
        v1.x = to_tf32(v1.x); v1.y = to_tf32(v1.y); v1.z = to_tf32(v1.z); v1.w = to_tf32(v1.w);
        *p0 = v0; *p1 = v1;
    }
    __syncthreads();

    const int wm = warp >> 1, wn = warp & 1;
    const int group = lane >> 2, tig = lane & 3;
    const int arow0 = wm * 16 + group;
    const int brow0 = wn * 64 + group;
    const int pgrp  = ((group & 3) << 1) | (group >> 2);

    float accg[8][4], accl[8][4];
    #pragma unroll
    for (int u = 0; u < 8; ++u)
        #pragma unroll
        for (int v = 0; v < 4; ++v) { accg[u][v] = 0.0f; accl[u][v] = 0.0f; }

    #pragma unroll
    for (int ks = 0; ks < 16; ++ks) {
        const int k = ks * 8;
        uint32_t a0 = __float_as_uint(zn[arow0 * PAD + k + tig]);
        uint32_t a1 = __float_as_uint(zn[(arow0 + 8) * PAD + k + tig]);
        uint32_t a2 = __float_as_uint(zn[arow0 * PAD + k + tig + 4]);
        uint32_t a3 = __float_as_uint(zn[(arow0 + 8) * PAD + k + tig + 4]);
        #pragma unroll
        for (int u = 0; u < 8; ++u) {
            int rb = brow0 + u * 8;
            uint32_t b0 = __float_as_uint(Wt0[(k + tig) * WSTR + rb]);
            uint32_t b1 = __float_as_uint(Wt0[(k + tig + 4) * WSTR + rb]);
            mma_tf32(accg[u], a0, a1, a2, a3, b0, b1);
        }
    }
    #pragma unroll
    for (int ks = 0; ks < 16; ++ks) {
        const int k = ks * 8;
        uint32_t a0 = __float_as_uint(zn[arow0 * PAD + k + tig]);
        uint32_t a1 = __float_as_uint(zn[(arow0 + 8) * PAD + k + tig]);
        uint32_t a2 = __float_as_uint(zn[arow0 * PAD + k + tig + 4]);
        uint32_t a3 = __float_as_uint(zn[(arow0 + 8) * PAD + k + tig + 4]);
        #pragma unroll
        for (int u = 0; u < 8; ++u) {
            int rb = brow0 + u * 8;
            uint32_t b0 = __float_as_uint(Wt1[(k + tig) * WSTR + rb]);
            uint32_t b1 = __float_as_uint(Wt1[(k + tig + 4) * WSTR + rb]);
            mma_tf32(accl[u], a0, a1, a2, a3, b0, b1);
        }
    }

    if (jobA) {
        const int rowp = bx * 128 + wm * 16 + pgrp;
        #pragma unroll
        for (int u = 0; u < 8; ++u) {
            const int col = wn * 64 + u * 8 + tig * 2;
            const float bg0 = bg[col], bg1 = bg[col + 1];
            const float bl0 = bl[col], bl1 = bl[col + 1];
            float v0 = to_tf32(sigmoidf_(accg[u][0] + bg0) * (accl[u][0] + bl0));
            float v1 = to_tf32(sigmoidf_(accg[u][1] + bg1) * (accl[u][1] + bl1));
            float v2 = to_tf32(sigmoidf_(accg[u][2] + bg0) * (accl[u][2] + bl0));
            float v3 = to_tf32(sigmoidf_(accg[u][3] + bg1) * (accl[u][3] + bl1));
            g_a[(size_t)col       * LLQ + rowp]     = v0;
            g_a[(size_t)(col + 1) * LLQ + rowp]     = v1;
            g_a[(size_t)col       * LLQ + rowp + 8] = v2;
            g_a[(size_t)(col + 1) * LLQ + rowp + 8] = v3;
        }
    } else {
        const int m0 = (bx & 3) * 128;
        const int j  = bx >> 2;
        const int mp = m0 + wm * 16 + pgrp;
        float* dst = g_bt + (size_t)j * LQ + mp;
        #pragma unroll
        for (int u = 0; u < 8; ++u) {
            const int col = wn * 64 + u * 8 + tig * 2;
            const float bg0 = bg[col], bg1 = bg[col + 1];
            const float bl0 = bl[col], bl1 = bl[col + 1];
            float v0 = to_tf32(sigmoidf_(accg[u][0] + bg0) * (accl[u][0] + bl0));
            float v1 = to_tf32(sigmoidf_(accg[u][1] + bg1) * (accl[u][1] + bl1));
            float v2 = to_tf32(sigmoidf_(accg[u][2] + bg0) * (accl[u][2] + bl0));
            float v3 = to_tf32(sigmoidf_(accg[u][3] + bg1) * (accl[u][3] + bl1));
            dst[(size_t)col       * LLQ]     = v0;
            dst[(size_t)(col + 1) * LLQ]     = v1;
            dst[(size_t)col       * LLQ + 8] = v2;
            dst[(size_t)(col + 1) * LLQ + 8] = v3;
        }
    }
}

// ---------------------------------------------------------------------------
// Kernel 2: 3-stage cp.async pipeline, 1 barrier per K-chunk.
// Per CTA: 128x128 tile of K_c = A_c @ B_c^T, BK=32, permuted-K layout.
// ---------------------------------------------------------------------------
#define EPAD 36
#define ESTG (128 * EPAD)   // floats per operand stage

__global__ void __launch_bounds__(256, 2) k_einsum_cp()
{
    extern __shared__ float es[];
    float* As = es;              // [3][ESTG]
    float* Bs = es + 3 * ESTG;   // [3][ESTG]

    const int tid  = threadIdx.x;
    const int lane = tid & 31, warp = tid >> 5;
    const int wm = warp & 3;
    const int wn = warp >> 2;
    const int c  = blockIdx.z;
    const int i0 = blockIdx.y * 128;
    const int j0 = blockIdx.x * 128;

    const float* A  = g_a  + (size_t)c * LLQ;
    const float* Bt = g_bt + (size_t)c * LLQ;

    const uint32_t sA = smem_u32(As);
    const uint32_t sB = smem_u32(Bs);

    int lrow[4], lq[4];
    #pragma unroll
    for (int r = 0; r < 4; ++r) {
        int idx = r * 256 + tid;
        lrow[r] = idx >> 3;
        lq[r]   = idx & 7;
    }

    // prologue: stages 0,1
    #pragma unroll
    for (int kt = 0; kt < 2; ++kt) {
        #pragma unroll
        for (int r = 0; r < 4; ++r) {
            uint32_t off = (uint32_t)(kt * ESTG + lrow[r] * EPAD + lq[r] * 4) * 4u;
            CP_ASYNC16(sA + off, A  + (size_t)(i0 + lrow[r]) * LQ + kt * 32 + lq[r] * 4);
            CP_ASYNC16(sB + off, Bt + (size_t)(j0 + lrow[r]) * LQ + kt * 32 + lq[r] * 4);
        }
        CP_COMMIT();
    }

    float acc[2][8][4];
    #pragma unroll
    for (int t = 0; t < 2; ++t)
        #pragma unroll
        for (int u = 0; u < 8; ++u)
            #pragma unroll
            for (int v = 0; v < 4; ++v) acc[t][u][v] = 0.0f;

    const int arow0 = wm * 32 + (lane >> 2);
    const int tig2  = (lane & 3) * 2;
    const int brow0 = wn * 64 + (lane >> 2);

    #pragma unroll 1
    for (int kt = 0; kt < 16; ++kt) {
        const int buf = kt % 3;
        if (kt < 15) { CP_WAIT1(); } else { CP_WAIT0(); }
        __syncthreads();   // stage kt data visible; all reads of stage kt-1 done

        // prefetch stage kt+2 into buf (kt+2)%3 (last read at iteration kt-1)
        if (kt + 2 < 16) {
            const int nk = kt + 2;
            const int nbuf = nk % 3;
            #pragma unroll
            for (int r = 0; r < 4; ++r) {
                uint32_t off = (uint32_t)(nbuf * ESTG + lrow[r] * EPAD + lq[r] * 4) * 4u;
                CP_ASYNC16(sA + off, A  + (size_t)(i0 + lrow[r]) * LQ + nk * 32 + lq[r] * 4);
                CP_ASYNC16(sB + off, Bt + (size_t)(j0 + lrow[r]) * LQ + nk * 32 + lq[r] * 4);
            }
            CP_COMMIT();
        }

        const float* Ab = As + buf * ESTG;
        const float* Bb = Bs + buf * ESTG;

        #pragma unroll
        for (int ks = 0; ks < 4; ++ks) {
            const int fo = ks * 8 + tig2;
            uint32_t af[2][4];
            #pragma unroll
            for (int t = 0; t < 2; ++t) {
                int ra = arow0 + t * 16;
                float2 fa0 = *(const float2*)(Ab + ra * EPAD + fo);
                float2 fa1 = *(const float2*)(Ab + (ra + 8) * EPAD + fo);
                af[t][0] = __float_as_uint(fa0.x); af[t][2] = __float_as_uint(fa0.y);
                af[t][1] = __float_as_uint(fa1.x); af[t][3] = __float_as_uint(fa1.y);
            }
            #pragma unroll
            for (int u = 0; u < 8; ++u) {
                int rb = brow0 + u * 8;
                float2 fb = *(const float2*)(Bb + rb * EPAD + fo);
                uint32_t b0 = __float_as_uint(fb.x), b1 = __float_as_uint(fb.y);
                mma_tf32(acc[0][u], af[0][0], af[0][1], af[0][2], af[0][3], b0, b1);
                mma_tf32(acc[1][u], af[1][0], af[1][1], af[1][2], af[1][3], b0, b1);
            }
        }
    }

    float* K = g_k + (size_t)c * LLQ;
    const int orow = i0 + wm * 32 + (lane >> 2);
    const int ocol = j0 + wn * 64 + (lane & 3) * 2;
    #pragma unroll
    for (int t = 0; t < 2; ++t) {
        #pragma unroll
        for (int u = 0; u < 8; ++u) {
            float* p0 = K + (size_t)(orow + t * 16)     * LQ + ocol + u * 8;
            float* p1 = K + (size_t)(orow + t * 16 + 8) * LQ + ocol + u * 8;
            *(float2*)p0 = make_float2(acc[t][u][0], acc[t][u][1]);
            *(float2*)p1 = make_float2(acc[t][u][2], acc[t][u][3]);
        }
    }
}

// ---------------------------------------------------------------------------
// Kernel 3: out = sigmoid(LN(z)@Wgo + bgo) * (LN(k)@Wlo + blo)
// ---------------------------------------------------------------------------
__global__ void __launch_bounds__(512, 1) k_final(
    const float* __restrict__ z,
    const float* __restrict__ lnw, const float* __restrict__ lnb,
    const float* __restrict__ lnow, const float* __restrict__ lnob,
    const float* __restrict__ Wgo, const float* __restrict__ bgo,
    const float* __restrict__ Wlo, const float* __restrict__ blo,
    float* __restrict__ out)
{
    extern __shared__ float sm[];
    float* buf = sm;                          // [128][PAD]: zn, then kn
    float* Wt0 = sm + 128 * PAD;              // [128][WSTR]
    float* Wt1 = sm + 128 * PAD + 128 * WSTR; // [128][WSTR]

    const int tid  = threadIdx.x;
    const int r0   = blockIdx.x * 128;
    const int i    = r0 >> 9;
    const int j0   = r0 & 511;
    const int lane = tid & 31, warp = tid >> 5;

    const uint32_t sW0 = smem_u32(Wt0);
    const uint32_t sW1 = smem_u32(Wt1);
    const uint32_t sBuf = smem_u32(buf);

    #pragma unroll
    for (int it = 0; it < 8; ++it) {
        int idx = it * 512 + tid;
        int k = idx >> 5, q = idx & 31;
        uint32_t off = (uint32_t)(k * WSTR + q * 4) * 4u;
        CP_ASYNC16(sW0 + off, Wgo + k * 128 + q * 4);
        CP_ASYNC16(sW1 + off, Wlo + k * 128 + q * 4);
    }
    CP_COMMIT();

    // LN(z) -> buf
    {
        const float w0 = lnw[lane], w1 = lnw[lane + 32], w2 = lnw[lane + 64], w3 = lnw[lane + 96];
        const float c0 = lnb[lane], c1 = lnb[lane + 32], c2 = lnb[lane + 64], c3 = lnb[lane + 96];
        for (int it = 0; it < 8; ++it) {
            int row = warp * 8 + it;
            const float* zr = z + (size_t)(r0 + row) * 128;
            float x0 = zr[lane], x1 = zr[lane + 32], x2 = zr[lane + 64], x3 = zr[lane + 96];
            float s = x0 + x1 + x2 + x3;
            float q = x0 * x0 + x1 * x1 + x2 * x2 + x3 * x3;
            #pragma unroll
            for (int o = 16; o > 0; o >>= 1) {
                s += __shfl_xor_sync(0xffffffffu, s, o);
                q += __shfl_xor_sync(0xffffffffu, q, o);
            }
            float mu  = s * (1.0f / 128.0f);
            float var = q * (1.0f / 128.0f) - mu * mu;
            float rs  = rsqrtf(var + 1e-5f);
            float* zo = buf + row * PAD;
            zo[lane]      = to_tf32((x0 - mu) * rs * w0 + c0);
            zo[lane + 32] = to_tf32((x1 - mu) * rs * w1 + c1);
            zo[lane + 64] = to_tf32((x2 - mu) * rs * w2 + c2);
            zo[lane + 96] = to_tf32((x3 - mu) * rs * w3 + c3);
        }
    }

    CP_WAIT0();
    __syncthreads();
    #pragma unroll
    for (int it = 0; it < 8; ++it) {
        int idx = it * 512 + tid;
        int k = idx >> 5, q = idx & 31;
        float4* p0 = (float4*)(Wt0 + k * WSTR + q * 4);
        float4* p1 = (float4*)(Wt1 + k * WSTR + q * 4);
        float4 v0 = *p0, v1 = *p1;
        v0.x = to_tf32(v0.x); v0.y = to_tf32(v0.y); v0.z = to_tf32(v0.z); v0.w = to_tf32(v0.w);
        v1.x = to_tf32(v1.x); v1.y = to_tf32(v1.y); v1.z = to_tf32(v1.z); v1.w = to_tf32(v1.w);
        *p0 = v0; *p1 = v1;
    }
    __syncthreads();

    const int wm = warp >> 1, wn = warp & 1;
    const int group = lane >> 2, tig = lane & 3;
    const int arow0 = wm * 16 + group;
    const int brow0 = wn * 64 + group;

    float accg[8][4];
    #pragma unroll
    for (int u = 0; u < 8; ++u)
        #pragma unroll
        for (int v = 0; v < 4; ++v) accg[u][v] = 0.0f;

    #pragma unroll
    for (int ks = 0; ks < 16; ++ks) {
        const int k = ks * 8;
        uint32_t a0 = __float_as_uint(buf[arow0 * PAD + k + tig]);
        uint32_t a1 = __float_as_uint(buf[(arow0 + 8) * PAD + k + tig]);
        uint32_t a2 = __float_as_uint(buf[arow0 * PAD + k + tig + 4]);
        uint32_t a3 = __float_as_uint(buf[(arow0 + 8) * PAD + k + tig + 4]);
        #pragma unroll
        for (int u = 0; u < 8; ++u) {
            int rb = brow0 + u * 8;
            uint32_t b0 = __float_as_uint(Wt0[(k + tig) * WSTR + rb]);
            uint32_t b1 = __float_as_uint(Wt0[(k + tig + 4) * WSTR + rb]);
            mma_tf32(accg[u], a0, a1, a2, a3, b0, b1);
        }
    }
    __syncthreads();

    #pragma unroll
    for (int it = 0; it < 32; ++it) {
        int idx = it * 512 + tid;
        int jl = idx & 127;
        int c  = idx >> 7;
        CP_ASYNC4(sBuf + (uint32_t)(jl * PAD + c) * 4u,
                  g_k + (size_t)c * LLQ + (size_t)i * LQ + j0 + jl);
    }
    CP_COMMIT();
    CP_WAIT0();
    __syncthreads();

    // LN(k) in place
    {
        const float w0 = lnow[lane], w1 = lnow[lane + 32], w2 = lnow[lane + 64], w3 = lnow[lane + 96];
        const float c0 = lnob[lane], c1 = lnob[lane + 32], c2 = lnob[lane + 64], c3 = lnob[lane + 96];
        for (int it = 0; it < 8; ++it) {
            int row = warp * 8 + it;
            float* kr = buf + row * PAD;
            float x0 = kr[lane], x1 = kr[lane + 32], x2 = kr[lane + 64], x3 = kr[lane + 96];
            float s = x0 + x1 + x2 + x3;
            float q = x0 * x0 + x1 * x1 + x2 * x2 + x3 * x3;
            #pragma unroll
            for (int o = 16; o > 0; o >>= 1) {
                s += __shfl_xor_sync(0xffffffffu, s, o);
                q += __shfl_xor_sync(0xffffffffu, q, o);
            }
            float mu  = s * (1.0f / 128.0f);
            float var = q * (1.0f / 128.0f) - mu * mu;
            float rs  = rsqrtf(var + 1e-5f);
            kr[lane]      = to_tf32((x0 - mu) * rs * w0 + c0);
            kr[lane + 32] = to_tf32((x1 - mu) * rs * w1 + c1);
            kr[lane + 64] = to_tf32((x2 - mu) * rs * w2 + c2);
            kr[lane + 96] = to_tf32((x3 - mu) * rs * w3 + c3);
        }
    }
    __syncthreads();

    float accl[8][4];
    #pragma unroll
    for (int u = 0; u < 8; ++u)
        #pragma unroll
        for (int v = 0; v < 4; ++v) accl[u][v] = 0.0f;

    #pragma unroll
    for (int ks = 0; ks < 16; ++ks) {
        const int k = ks * 8;
        uint32_t a0 = __float_as_uint(buf[arow0 * PAD + k + tig]);
        uint32_t a1 = __float_as_uint(buf[(arow0 + 8) * PAD + k + tig]);
        uint32_t a2 = __float_as_uint(buf[arow0 * PAD + k + tig + 4]);
        uint32_t a3 = __float_as_uint(buf[(arow0 + 8) * PAD + k + tig + 4]);
        #pragma unroll
        for (int u = 0; u < 8; ++u) {
            int rb = brow0 + u * 8;
            uint32_t b0 = __float_as_uint(Wt1[(k + tig) * WSTR + rb]);
            uint32_t b1 = __float_as_uint(Wt1[(k + tig + 4) * WSTR + rb]);
            mma_tf32(accl[u], a0, a1, a2, a3, b0, b1);
        }
    }

    #pragma unroll
    for (int u = 0; u < 8; ++u) {
        const int col = wn * 64 + u * 8 + tig * 2;
        const float bg0 = bgo[col], bg1 = bgo[col + 1];
        const float bl0 = blo[col], bl1 = blo[col + 1];
        const int row = r0 + wm * 16 + group;
        float v0 = sigmoidf_(accg[u][0] + bg0) * (accl[u][0] + bl0);
        float v1 = sigmoidf_(accg[u][1] + bg1) * (accl[u][1] + bl1);
        float v2 = sigmoidf_(accg[u][2] + bg0) * (accl[u][2] + bl0);
        float v3 = sigmoidf_(accg[u][3] + bg1) * (accl[u][3] + bl1);
        *(float2*)(out + (size_t)row * 128 + col)       = make_float2(v0, v1);
        *(float2*)(out + (size_t)(row + 8) * 128 + col) = make_float2(v2, v3);
    }
}

// ---------------------------------------------------------------------------
extern "C" void kernel_launch(void* const* d_in, const int* in_sizes, int n_in,
                              void* d_out, int out_size)
{
    const float* z    = (const float*)d_in[0];
    const float* lnw  = (const float*)d_in[1];
    const float* lnb  = (const float*)d_in[2];
    const float* Wga  = (const float*)d_in[3];
    const float* bga  = (const float*)d_in[4];
    const float* Wla  = (const float*)d_in[5];
    const float* bla  = (const float*)d_in[6];
    const float* Wgb  = (const float*)d_in[7];
    const float* bgb  = (const float*)d_in[8];
    const float* Wlb  = (const float*)d_in[9];
    const float* blb  = (const float*)d_in[10];
    const float* lnow = (const float*)d_in[11];
    const float* lnob = (const float*)d_in[12];
    const float* Wgo  = (const float*)d_in[13];
    const float* bgo  = (const float*)d_in[14];
    const float* Wlo  = (const float*)d_in[15];
    const float* blo  = (const float*)d_in[16];
    float* out = (float*)d_out;

    const size_t smem13 = (size_t)(128 * PAD + 2 * 128 * WSTR) * sizeof(float);  // 206848
    const size_t smemE  = (size_t)(6 * ESTG) * sizeof(float);                    // 110592
    cudaFuncSetAttribute(k_proj_merged, cudaFuncAttributeMaxDynamicSharedMemorySize, (int)smem13);
    cudaFuncSetAttribute(k_einsum_cp,   cudaFuncAttributeMaxDynamicSharedMemorySize, (int)smemE);
    cudaFuncSetAttribute(k_final,       cudaFuncAttributeMaxDynamicSharedMemorySize, (int)smem13);

    k_proj_merged<<<4096, 512, smem13>>>(z, lnw, lnb, Wga, bga, Wla, bla, Wgb, bgb, Wlb, blb);
    k_einsum_cp<<<dim3(4, 4, 128), 256, smemE>>>();
    k_final<<<2048, 512, smem13>>>(z, lnw, lnb, lnow, lnob, Wgo, bgo, Wlo, blo, out);
}

// round 13
// speedup vs baseline: 1.1272x; 1.1272x over previous
#include <cuda_runtime.h>
#include <cstdint>

#define LQ 512
#define LLQ (512*512)
#define PAD 132    // proj: activation stride (4g+t clean)
#define WSTR 136   // proj: weight stride (8t+g clean)
#define FPAD 140   // k_final: universal stride (12g+t and 12t+g both clean)

// scratch. g_a and g_bt have the K dim (m) PERMUTED within 8-blocks:
// pos = (m&~7) | ((m&3)<<1) | ((m>>2)&1)
__device__ float g_a [(size_t)128 * LLQ];   // a [c][i][perm(m)] (tf32)
__device__ float g_bt[(size_t)128 * LLQ];   // b^T [c][j][perm(m)] (tf32)
__device__ float g_k [(size_t)128 * LLQ];   // k [c][i][j]       (fp32, plain)

__device__ __forceinline__ float sigmoidf_(float x) {
    return 1.0f / (1.0f + __expf(-x));
}
__device__ __forceinline__ float to_tf32(float x) {
    uint32_t u;
    asm("cvt.rna.tf32.f32 %0, %1;" : "=r"(u) : "f"(x));
    return __uint_as_float(u);
}
__device__ __forceinline__ uint32_t smem_u32(const void* p) {
    uint32_t a;
    asm("{ .reg .u64 t; cvta.to.shared.u64 t, %1; cvt.u32.u64 %0, t; }" : "=r"(a) : "l"(p));
    return a;
}
__device__ __forceinline__ void mma_tf32(float* d, uint32_t a0, uint32_t a1, uint32_t a2, uint32_t a3,
                                         uint32_t b0, uint32_t b1) {
    asm volatile(
        "mma.sync.aligned.m16n8k8.row.col.f32.tf32.tf32.f32 "
        "{%0,%1,%2,%3}, {%4,%5,%6,%7}, {%8,%9}, {%0,%1,%2,%3};"
        : "+f"(d[0]), "+f"(d[1]), "+f"(d[2]), "+f"(d[3])
        : "r"(a0), "r"(a1), "r"(a2), "r"(a3), "r"(b0), "r"(b1));
}

#define CP_ASYNC16(dst, src) \
    asm volatile("cp.async.ca.shared.global [%0], [%1], 16;" :: "r"(dst), "l"(src) : "memory")
#define CP_ASYNC4(dst, src) \
    asm volatile("cp.async.ca.shared.global [%0], [%1], 4;"  :: "r"(dst), "l"(src) : "memory")
#define CP_COMMIT() asm volatile("cp.async.commit_group;" ::: "memory")
#define CP_WAIT1()  asm volatile("cp.async.wait_group 1;"  ::: "memory")
#define CP_WAIT0()  asm volatile("cp.async.wait_group 0;"  ::: "memory")

// ---------------------------------------------------------------------------
// Kernel 1a (R11): LN(z) + gated projection (a-pair) -> g_a [c][i][perm(m)]
// ---------------------------------------------------------------------------
__global__ void __launch_bounds__(512, 1) k_proj_a(
    const float* __restrict__ z,
    const float* __restrict__ lnw, const float* __restrict__ lnb,
    const float* __restrict__ Wg, const float* __restrict__ bg,
    const float* __restrict__ Wl, const float* __restrict__ bl)
{
    extern __shared__ float sm[];
    float* zn  = sm;                          // [128][PAD]
    float* Wt0 = sm + 128 * PAD;              // [128][WSTR]
    float* Wt1 = sm + 128 * PAD + 128 * WSTR; // [128][WSTR]

    const int tid  = threadIdx.x;
    const int r0   = blockIdx.x * 128;
    const int lane = tid & 31, warp = tid >> 5;
    const uint32_t sW0 = smem_u32(Wt0);
    const uint32_t sW1 = smem_u32(Wt1);

    #pragma unroll
    for (int it = 0; it < 8; ++it) {
        int idx = it * 512 + tid;
        int k = idx >> 5, q = idx & 31;
        uint32_t off = (uint32_t)(k * WSTR + q * 4) * 4u;
        CP_ASYNC16(sW0 + off, Wg + k * 128 + q * 4);
        CP_ASYNC16(sW1 + off, Wl + k * 128 + q * 4);
    }
    CP_COMMIT();

    {
        const float w0 = lnw[lane], w1 = lnw[lane + 32], w2 = lnw[lane + 64], w3 = lnw[lane + 96];
        const float c0 = lnb[lane], c1 = lnb[lane + 32], c2 = lnb[lane + 64], c3 = lnb[lane + 96];
        for (int it = 0; it < 8; ++it) {
            int row = warp * 8 + it;
            const float* zr = z + (size_t)(r0 + row) * 128;
            float x0 = zr[lane], x1 = zr[lane + 32], x2 = zr[lane + 64], x3 = zr[lane + 96];
            float s = x0 + x1 + x2 + x3;
            float q = x0 * x0 + x1 * x1 + x2 * x2 + x3 * x3;
            #pragma unroll
            for (int o = 16; o > 0; o >>= 1) {
                s += __shfl_xor_sync(0xffffffffu, s, o);
                q += __shfl_xor_sync(0xffffffffu, q, o);
            }
            float mu  = s * (1.0f / 128.0f);
            float var = q * (1.0f / 128.0f) - mu * mu;
            float rs  = rsqrtf(var + 1e-5f);
            float* zo = zn + row * PAD;
            zo[lane]      = to_tf32((x0 - mu) * rs * w0 + c0);
            zo[lane + 32] = to_tf32((x1 - mu) * rs * w1 + c1);
            zo[lane + 64] = to_tf32((x2 - mu) * rs * w2 + c2);
            zo[lane + 96] = to_tf32((x3 - mu) * rs * w3 + c3);
        }
    }

    CP_WAIT0();
    __syncthreads();
    #pragma unroll
    for (int it = 0; it < 8; ++it) {
        int idx = it * 512 + tid;
        int k = idx >> 5, q = idx & 31;
        float4* p0 = (float4*)(Wt0 + k * WSTR + q * 4);
        float4* p1 = (float4*)(Wt1 + k * WSTR + q * 4);
        float4 v0 = *p0, v1 = *p1;
        v0.x = to_tf32(v0.x); v0.y = to_tf32(v0.y); v0.z = to_tf32(v0.z); v0.w = to_tf32(v0.w);
        v1.x = to_tf32(v1.x); v1.y = to_tf32(v1.y); v1.z = to_tf32(v1.z); v1.w = to_tf32(v1.w);
        *p0 = v0; *p1 = v1;
    }
    __syncthreads();

    const int wm = warp >> 1, wn = warp & 1;
    const int group = lane >> 2, tig = lane & 3;
    const int arow0 = wm * 16 + group;
    const int brow0 = wn * 64 + group;
    const int pgrp  = ((group & 3) << 1) | (group >> 2);

    float accg[8][4], accl[8][4];
    #pragma unroll
    for (int u = 0; u < 8; ++u)
        #pragma unroll
        for (int v = 0; v < 4; ++v) { accg[u][v] = 0.0f; accl[u][v] = 0.0f; }

    #pragma unroll
    for (int ks = 0; ks < 16; ++ks) {
        const int k = ks * 8;
        uint32_t a0 = __float_as_uint(zn[arow0 * PAD + k + tig]);
        uint32_t a1 = __float_as_uint(zn[(arow0 + 8) * PAD + k + tig]);
        uint32_t a2 = __float_as_uint(zn[arow0 * PAD + k + tig + 4]);
        uint32_t a3 = __float_as_uint(zn[(arow0 + 8) * PAD + k + tig + 4]);
        #pragma unroll
        for (int u = 0; u < 8; ++u) {
            int rb = brow0 + u * 8;
            uint32_t b0 = __float_as_uint(Wt0[(k + tig) * WSTR + rb]);
            uint32_t b1 = __float_as_uint(Wt0[(k + tig + 4) * WSTR + rb]);
            mma_tf32(accg[u], a0, a1, a2, a3, b0, b1);
        }
    }
    #pragma unroll
    for (int ks = 0; ks < 16; ++ks) {
        const int k = ks * 8;
        uint32_t a0 = __float_as_uint(zn[arow0 * PAD + k + tig]);
        uint32_t a1 = __float_as_uint(zn[(arow0 + 8) * PAD + k + tig]);
        uint32_t a2 = __float_as_uint(zn[arow0 * PAD + k + tig + 4]);
        uint32_t a3 = __float_as_uint(zn[(arow0 + 8) * PAD + k + tig + 4]);
        #pragma unroll
        for (int u = 0; u < 8; ++u) {
            int rb = brow0 + u * 8;
            uint32_t b0 = __float_as_uint(Wt1[(k + tig) * WSTR + rb]);
            uint32_t b1 = __float_as_uint(Wt1[(k + tig + 4) * WSTR + rb]);
            mma_tf32(accl[u], a0, a1, a2, a3, b0, b1);
        }
    }

    const int rowp = r0 + wm * 16 + pgrp;
    #pragma unroll
    for (int u = 0; u < 8; ++u) {
        const int col = wn * 64 + u * 8 + tig * 2;
        const float bg0 = bg[col], bg1 = bg[col + 1];
        const float bl0 = bl[col], bl1 = bl[col + 1];
        float v0 = to_tf32(sigmoidf_(accg[u][0] + bg0) * (accl[u][0] + bl0));
        float v1 = to_tf32(sigmoidf_(accg[u][1] + bg1) * (accl[u][1] + bl1));
        float v2 = to_tf32(sigmoidf_(accg[u][2] + bg0) * (accl[u][2] + bl0));
        float v3 = to_tf32(sigmoidf_(accg[u][3] + bg1) * (accl[u][3] + bl1));
        g_a[(size_t)col       * LLQ + rowp]     = v0;
        g_a[(size_t)(col + 1) * LLQ + rowp]     = v1;
        g_a[(size_t)col       * LLQ + rowp + 8] = v2;
        g_a[(size_t)(col + 1) * LLQ + rowp + 8] = v3;
    }
}

// ---------------------------------------------------------------------------
// Kernel 1b (R11): LN(z) + gated projection (b-pair) -> g_bt [c][j][perm(m)]
// ---------------------------------------------------------------------------
__global__ void __launch_bounds__(512, 1) k_proj_bt(
    const float* __restrict__ z,
    const float* __restrict__ lnw, const float* __restrict__ lnb,
    const float* __restrict__ Wg, const float* __restrict__ bg,
    const float* __restrict__ Wl, const float* __restrict__ bl)
{
    extern __shared__ float sm[];
    float* zn  = sm;
    float* Wt0 = sm + 128 * PAD;
    float* Wt1 = sm + 128 * PAD + 128 * WSTR;

    const int tid  = threadIdx.x;
    const int m0   = (blockIdx.x & 3) * 128;
    const int j    = blockIdx.x >> 2;
    const int lane = tid & 31, warp = tid >> 5;
    const uint32_t sW0 = smem_u32(Wt0);
    const uint32_t sW1 = smem_u32(Wt1);

    #pragma unroll
    for (int it = 0; it < 8; ++it) {
        int idx = it * 512 + tid;
        int k = idx >> 5, q = idx & 31;
        uint32_t off = (uint32_t)(k * WSTR + q * 4) * 4u;
        CP_ASYNC16(sW0 + off, Wg + k * 128 + q * 4);
        CP_ASYNC16(sW1 + off, Wl + k * 128 + q * 4);
    }
    CP_COMMIT();

    {
        const float w0 = lnw[lane], w1 = lnw[lane + 32], w2 = lnw[lane + 64], w3 = lnw[lane + 96];
        const float c0 = lnb[lane], c1 = lnb[lane + 32], c2 = lnb[lane + 64], c3 = lnb[lane + 96];
        for (int it = 0; it < 8; ++it) {
            int row = warp * 8 + it;
            const float* zr = z + ((size_t)(m0 + row) * LQ + j) * 128;
            float x0 = zr[lane], x1 = zr[lane + 32], x2 = zr[lane + 64], x3 = zr[lane + 96];
            float s = x0 + x1 + x2 + x3;
            float q = x0 * x0 + x1 * x1 + x2 * x2 + x3 * x3;
            #pragma unroll
            for (int o = 16; o > 0; o >>= 1) {
                s += __shfl_xor_sync(0xffffffffu, s, o);
                q += __shfl_xor_sync(0xffffffffu, q, o);
            }
            float mu  = s * (1.0f / 128.0f);
            float var = q * (1.0f / 128.0f) - mu * mu;
            float rs  = rsqrtf(var + 1e-5f);
            float* zo = zn + row * PAD;
            zo[lane]      = to_tf32((x0 - mu) * rs * w0 + c0);
            zo[lane + 32] = to_tf32((x1 - mu) * rs * w1 + c1);
            zo[lane + 64] = to_tf32((x2 - mu) * rs * w2 + c2);
            zo[lane + 96] = to_tf32((x3 - mu) * rs * w3 + c3);
        }
    }

    CP_WAIT0();
    __syncthreads();
    #pragma unroll
    for (int it = 0; it < 8; ++it) {
        int idx = it * 512 + tid;
        int k = idx >> 5, q = idx & 31;
        float4* p0 = (float4*)(Wt0 + k * WSTR + q * 4);
        float4* p1 = (float4*)(Wt1 + k * WSTR + q * 4);
        float4 v0 = *p0, v1 = *p1;
        v0.x = to_tf32(v0.x); v0.y = to_tf32(v0.y); v0.z = to_tf32(v0.z); v0.w = to_tf32(v0.w);
        v1.x = to_tf32(v1.x); v1.y = to_tf32(v1.y); v1.z = to_tf32(v1.z); v1.w = to_tf32(v1.w);
        *p0 = v0; *p1 = v1;
    }
    __syncthreads();

    const int wm = warp >> 1, wn = warp & 1;
    const int group = lane >> 2, tig = lane & 3;
    const int arow0 = wm * 16 + group;
    const int brow0 = wn * 64 + group;
    const int pgrp  = ((group & 3) << 1) | (group >> 2);

    float accg[8][4], accl[8][4];
    #pragma unroll
    for (int u = 0; u < 8; ++u)
        #pragma unroll
        for (int v = 0; v < 4; ++v) { accg[u][v] = 0.0f; accl[u][v] = 0.0f; }

    #pragma unroll
    for (int ks = 0; ks < 16; ++ks) {
        const int k = ks * 8;
        uint32_t a0 = __float_as_uint(zn[arow0 * PAD + k + tig]);
        uint32_t a1 = __float_as_uint(zn[(arow0 + 8) * PAD + k + tig]);
        uint32_t a2 = __float_as_uint(zn[arow0 * PAD + k + tig + 4]);
        uint32_t a3 = __float_as_uint(zn[(arow0 + 8) * PAD + k + tig + 4]);
        #pragma unroll
        for (int u = 0; u < 8; ++u) {
            int rb = brow0 + u * 8;
            uint32_t b0 = __float_as_uint(Wt0[(k + tig) * WSTR + rb]);
            uint32_t b1 = __float_as_uint(Wt0[(k + tig + 4) * WSTR + rb]);
            mma_tf32(accg[u], a0, a1, a2, a3, b0, b1);
        }
    }
    #pragma unroll
    for (int ks = 0; ks < 16; ++ks) {
        const int k = ks * 8;
        uint32_t a0 = __float_as_uint(zn[arow0 * PAD + k + tig]);
        uint32_t a1 = __float_as_uint(zn[(arow0 + 8) * PAD + k + tig]);
        uint32_t a2 = __float_as_uint(zn[arow0 * PAD + k + tig + 4]);
        uint32_t a3 = __float_as_uint(zn[(arow0 + 8) * PAD + k + tig + 4]);
        #pragma unroll
        for (int u = 0; u < 8; ++u) {
            int rb = brow0 + u * 8;
            uint32_t b0 = __float_as_uint(Wt1[(k + tig) * WSTR + rb]);
            uint32_t b1 = __float_as_uint(Wt1[(k + tig + 4) * WSTR + rb]);
            mma_tf32(accl[u], a0, a1, a2, a3, b0, b1);
        }
    }

    const int mp = m0 + wm * 16 + pgrp;
    float* dst = g_bt + (size_t)j * LQ + mp;
    #pragma unroll
    for (int u = 0; u < 8; ++u) {
        const int col = wn * 64 + u * 8 + tig * 2;
        const float bg0 = bg[col], bg1 = bg[col + 1];
        const float bl0 = bl[col], bl1 = bl[col + 1];
        float v0 = to_tf32(sigmoidf_(accg[u][0] + bg0) * (accl[u][0] + bl0));
        float v1 = to_tf32(sigmoidf_(accg[u][1] + bg1) * (accl[u][1] + bl1));
        float v2 = to_tf32(sigmoidf_(accg[u][2] + bg0) * (accl[u][2] + bl0));
        float v3 = to_tf32(sigmoidf_(accg[u][3] + bg1) * (accl[u][3] + bl1));
        dst[(size_t)col       * LLQ]     = v0;
        dst[(size_t)(col + 1) * LLQ]     = v1;
        dst[(size_t)col       * LLQ + 8] = v2;
        dst[(size_t)(col + 1) * LLQ + 8] = v3;
    }
}

// ---------------------------------------------------------------------------
// Kernel 2 (R11): 2-stage cp.async mma.sync TF32 einsum, permuted-K, EPAD 40.
// ---------------------------------------------------------------------------
#define EPAD 40
#define ESTG (128 * EPAD)

__global__ void __launch_bounds__(256, 2) k_einsum_cp()
{
    extern __shared__ float es[];
    float* As = es;
    float* Bs = es + 2 * ESTG;

    const int tid  = threadIdx.x;
    const int lane = tid & 31, warp = tid >> 5;
    const int wm = warp & 3;
    const int wn = warp >> 2;
    const int c  = blockIdx.z;
    const int i0 = blockIdx.y * 128;
    const int j0 = blockIdx.x * 128;

    const float* A  = g_a  + (size_t)c * LLQ;
    const float* Bt = g_bt + (size_t)c * LLQ;

    const uint32_t sA = smem_u32(As);
    const uint32_t sB = smem_u32(Bs);

    int lrow[4], lq[4];
    #pragma unroll
    for (int r = 0; r < 4; ++r) {
        int idx = r * 256 + tid;
        lrow[r] = idx >> 3;
        lq[r]   = idx & 7;
    }

    #pragma unroll
    for (int kt = 0; kt < 2; ++kt) {
        #pragma unroll
        for (int r = 0; r < 4; ++r) {
            uint32_t off = (uint32_t)(kt * ESTG + lrow[r] * EPAD + lq[r] * 4) * 4u;
            CP_ASYNC16(sA + off, A  + (size_t)(i0 + lrow[r]) * LQ + kt * 32 + lq[r] * 4);
            CP_ASYNC16(sB + off, Bt + (size_t)(j0 + lrow[r]) * LQ + kt * 32 + lq[r] * 4);
        }
        CP_COMMIT();
    }

    float acc[2][8][4];
    #pragma unroll
    for (int t = 0; t < 2; ++t)
        #pragma unroll
        for (int u = 0; u < 8; ++u)
            #pragma unroll
            for (int v = 0; v < 4; ++v) acc[t][u][v] = 0.0f;

    const int arow0 = wm * 32 + (lane >> 2);
    const int tig2  = (lane & 3) * 2;
    const int brow0 = wn * 64 + (lane >> 2);

    #pragma unroll 1
    for (int kt = 0; kt < 16; ++kt) {
        const int buf = kt & 1;
        if (kt < 14) { CP_WAIT1(); } else { CP_WAIT0(); }
        __syncthreads();

        const float* Ab = As + buf * ESTG;
        const float* Bb = Bs + buf * ESTG;

        #pragma unroll
        for (int ks = 0; ks < 4; ++ks) {
            const int fo = ks * 8 + tig2;
            uint32_t af[2][4];
            #pragma unroll
            for (int t = 0; t < 2; ++t) {
                int ra = arow0 + t * 16;
                float2 fa0 = *(const float2*)(Ab + ra * EPAD + fo);
                float2 fa1 = *(const float2*)(Ab + (ra + 8) * EPAD + fo);
                af[t][0] = __float_as_uint(fa0.x); af[t][2] = __float_as_uint(fa0.y);
                af[t][1] = __float_as_uint(fa1.x); af[t][3] = __float_as_uint(fa1.y);
            }
            #pragma unroll
            for (int u = 0; u < 8; ++u) {
                int rb = brow0 + u * 8;
                float2 fb = *(const float2*)(Bb + rb * EPAD + fo);
                uint32_t b0 = __float_as_uint(fb.x), b1 = __float_as_uint(fb.y);
                mma_tf32(acc[0][u], af[0][0], af[0][1], af[0][2], af[0][3], b0, b1);
                mma_tf32(acc[1][u], af[1][0], af[1][1], af[1][2], af[1][3], b0, b1);
            }
        }
        __syncthreads();

        if (kt + 2 < 16) {
            const int nk = kt + 2;
            #pragma unroll
            for (int r = 0; r < 4; ++r) {
                uint32_t off = (uint32_t)(buf * ESTG + lrow[r] * EPAD + lq[r] * 4) * 4u;
                CP_ASYNC16(sA + off, A  + (size_t)(i0 + lrow[r]) * LQ + nk * 32 + lq[r] * 4);
                CP_ASYNC16(sB + off, Bt + (size_t)(j0 + lrow[r]) * LQ + nk * 32 + lq[r] * 4);
            }
            CP_COMMIT();
        }
    }

    float* K = g_k + (size_t)c * LLQ;
    const int orow = i0 + wm * 32 + (lane >> 2);
    const int ocol = j0 + wn * 64 + (lane & 3) * 2;
    #pragma unroll
    for (int t = 0; t < 2; ++t) {
        #pragma unroll
        for (int u = 0; u < 8; ++u) {
            float* p0 = K + (size_t)(orow + t * 16)     * LQ + ocol + u * 8;
            float* p1 = K + (size_t)(orow + t * 16 + 8) * LQ + ocol + u * 8;
            *(float2*)p0 = make_float2(acc[t][u][0], acc[t][u][1]);
            *(float2*)p1 = make_float2(acc[t][u][2], acc[t][u][3]);
        }
    }
}

// ---------------------------------------------------------------------------
// Kernel 3: out = sigmoid(LN(z)@Wgo + bgo) * (LN(k)@Wlo + blo)
// Overlapped: kn gather issued at entry (overlaps LN(z)+gate GEMM);
// Wlo load overlaps LN(k) by reusing the dead zn region. Stride FPAD=140
// is conflict-free for both activation and weight fragment reads.
// ---------------------------------------------------------------------------
__global__ void __launch_bounds__(512, 1) k_final(
    const float* __restrict__ z,
    const float* __restrict__ lnw, const float* __restrict__ lnb,
    const float* __restrict__ lnow, const float* __restrict__ lnob,
    const float* __restrict__ Wgo, const float* __restrict__ bgo,
    const float* __restrict__ Wlo, const float* __restrict__ blo,
    float* __restrict__ out)
{
    extern __shared__ float sm[];
    float* zn  = sm;                   // [128][FPAD]; later reused for Wlo
    float* Wt0 = sm + 128 * FPAD;      // [128][FPAD]  Wgo
    float* kn  = sm + 2 * 128 * FPAD;  // [128][FPAD]
    float* Wt1 = zn;                   // alias: Wlo after gate GEMM

    const int tid  = threadIdx.x;
    const int r0   = blockIdx.x * 128;
    const int i    = r0 >> 9;
    const int j0   = r0 & 511;
    const int lane = tid & 31, warp = tid >> 5;

    const uint32_t sZn = smem_u32(zn);
    const uint32_t sW0 = smem_u32(Wt0);
    const uint32_t sKn = smem_u32(kn);

    // group0: Wgo
    #pragma unroll
    for (int it = 0; it < 8; ++it) {
        int idx = it * 512 + tid;
        int k = idx >> 5, q = idx & 31;
        CP_ASYNC16(sW0 + (uint32_t)(k * FPAD + q * 4) * 4u, Wgo + k * 128 + q * 4);
    }
    CP_COMMIT();
    // group1: kn gather (overlaps LN(z) + gate GEMM)
    #pragma unroll
    for (int it = 0; it < 32; ++it) {
        int idx = it * 512 + tid;
        int jl = idx & 127;
        int c  = idx >> 7;
        CP_ASYNC4(sKn + (uint32_t)(jl * FPAD + c) * 4u,
                  g_k + (size_t)c * LLQ + (size_t)i * LQ + j0 + jl);
    }
    CP_COMMIT();

    // LN(z) -> zn
    {
        const float w0 = lnw[lane], w1 = lnw[lane + 32], w2 = lnw[lane + 64], w3 = lnw[lane + 96];
        const float c0 = lnb[lane], c1 = lnb[lane + 32], c2 = lnb[lane + 64], c3 = lnb[lane + 96];
        for (int it = 0; it < 8; ++it) {
            int row = warp * 8 + it;
            const float* zr = z + (size_t)(r0 + row) * 128;
            float x0 = zr[lane], x1 = zr[lane + 32], x2 = zr[lane + 64], x3 = zr[lane + 96];
            float s = x0 + x1 + x2 + x3;
            float q = x0 * x0 + x1 * x1 + x2 * x2 + x3 * x3;
            #pragma unroll
            for (int o = 16; o > 0; o >>= 1) {
                s += __shfl_xor_sync(0xffffffffu, s, o);
                q += __shfl_xor_sync(0xffffffffu, q, o);
            }
            float mu  = s * (1.0f / 128.0f);
            float var = q * (1.0f / 128.0f) - mu * mu;
            float rs  = rsqrtf(var + 1e-5f);
            float* zo = zn + row * FPAD;
            zo[lane]      = to_tf32((x0 - mu) * rs * w0 + c0);
            zo[lane + 32] = to_tf32((x1 - mu) * rs * w1 + c1);
            zo[lane + 64] = to_tf32((x2 - mu) * rs * w2 + c2);
            zo[lane + 96] = to_tf32((x3 - mu) * rs * w3 + c3);
        }
    }

    CP_WAIT1();      // Wgo arrived (kn may still be in flight)
    __syncthreads();
    // round Wgo in place
    #pragma unroll
    for (int it = 0; it < 8; ++it) {
        int idx = it * 512 + tid;
        int k = idx >> 5, q = idx & 31;
        float4* p0 = (float4*)(Wt0 + k * FPAD + q * 4);
        float4 v0 = *p0;
        v0.x = to_tf32(v0.x); v0.y = to_tf32(v0.y); v0.z = to_tf32(v0.z); v0.w = to_tf32(v0.w);
        *p0 = v0;
    }
    __syncthreads();

    const int wm = warp >> 1, wn = warp & 1;
    const int group = lane >> 2, tig = lane & 3;
    const int arow0 = wm * 16 + group;
    const int brow0 = wn * 64 + group;

    // gate GEMM: zn x Wgo
    float accg[8][4];
    #pragma unroll
    for (int u = 0; u < 8; ++u)
        #pragma unroll
        for (int v = 0; v < 4; ++v) accg[u][v] = 0.0f;

    #pragma unroll
    for (int ks = 0; ks < 16; ++ks) {
        const int k = ks * 8;
        uint32_t a0 = __float_as_uint(zn[arow0 * FPAD + k + tig]);
        uint32_t a1 = __float_as_uint(zn[(arow0 + 8) * FPAD + k + tig]);
        uint32_t a2 = __float_as_uint(zn[arow0 * FPAD + k + tig + 4]);
        uint32_t a3 = __float_as_uint(zn[(arow0 + 8) * FPAD + k + tig + 4]);
        #pragma unroll
        for (int u = 0; u < 8; ++u) {
            int rb = brow0 + u * 8;
            uint32_t b0 = __float_as_uint(Wt0[(k + tig) * FPAD + rb]);
            uint32_t b1 = __float_as_uint(Wt0[(k + tig + 4) * FPAD + rb]);
            mma_tf32(accg[u], a0, a1, a2, a3, b0, b1);
        }
    }
    __syncthreads();   // zn reads complete; region free for Wlo

    // group2: Wlo -> zn region (overlaps LN(k))
    #pragma unroll
    for (int it = 0; it < 8; ++it) {
        int idx = it * 512 + tid;
        int k = idx >> 5, q = idx & 31;
        CP_ASYNC16(sZn + (uint32_t)(k * FPAD + q * 4) * 4u, Wlo + k * 128 + q * 4);
    }
    CP_COMMIT();

    CP_WAIT1();       // kn gather complete (Wlo may still be in flight)
    __syncthreads();

    // LN(k) in place in kn
    {
        const float w0 = lnow[lane], w1 = lnow[lane + 32], w2 = lnow[lane + 64], w3 = lnow[lane + 96];
        const float c0 = lnob[lane], c1 = lnob[lane + 32], c2 = lnob[lane + 64], c3 = lnob[lane + 96];
        for (int it = 0; it < 8; ++it) {
            int row = warp * 8 + it;
            float* kr = kn + row * FPAD;
            float x0 = kr[lane], x1 = kr[lane + 32], x2 = kr[lane + 64], x3 = kr[lane + 96];
            float s = x0 + x1 + x2 + x3;
            float q = x0 * x0 + x1 * x1 + x2 * x2 + x3 * x3;
            #pragma unroll
            for (int o = 16; o > 0; o >>= 1) {
                s += __shfl_xor_sync(0xffffffffu, s, o);
                q += __shfl_xor_sync(0xffffffffu, q, o);
            }
            float mu  = s * (1.0f / 128.0f);
            float var = q * (1.0f / 128.0f) - mu * mu;
            float rs  = rsqrtf(var + 1e-5f);
            kr[lane]      = to_tf32((x0 - mu) * rs * w0 + c0);
            kr[lane + 32] = to_tf32((x1 - mu) * rs * w1 + c1);
            kr[lane + 64] = to_tf32((x2 - mu) * rs * w2 + c2);
            kr[lane + 96] = to_tf32((x3 - mu) * rs * w3 + c3);
        }
    }

    CP_WAIT0();       // Wlo arrived
    __syncthreads();
    // round Wlo in place
    #pragma unroll
    for (int it = 0; it < 8; ++it) {
        int idx = it * 512 + tid;
        int k = idx >> 5, q = idx & 31;
        float4* p1 = (float4*)(Wt1 + k * FPAD + q * 4);
        float4 v1 = *p1;
        v1.x = to_tf32(v1.x); v1.y = to_tf32(v1.y); v1.z = to_tf32(v1.z); v1.w = to_tf32(v1.w);
        *p1 = v1;
    }
    __syncthreads();

    // linear GEMM: kn x Wlo
    float accl[8][4];
    #pragma unroll
    for (int u = 0; u < 8; ++u)
        #pragma unroll
        for (int v = 0; v < 4; ++v) accl[u][v] = 0.0f;

    #pragma unroll
    for (int ks = 0; ks < 16; ++ks) {
        const int k = ks * 8;
        uint32_t a0 = __float_as_uint(kn[arow0 * FPAD + k + tig]);
        uint32_t a1 = __float_as_uint(kn[(arow0 + 8) * FPAD + k + tig]);
        uint32_t a2 = __float_as_uint(kn[arow0 * FPAD + k + tig + 4]);
        uint32_t a3 = __float_as_uint(kn[(arow0 + 8) * FPAD + k + tig + 4]);
        #pragma unroll
        for (int u = 0; u < 8; ++u) {
            int rb = brow0 + u * 8;
            uint32_t b0 = __float_as_uint(Wt1[(k + tig) * FPAD + rb]);
            uint32_t b1 = __float_as_uint(Wt1[(k + tig + 4) * FPAD + rb]);
            mma_tf32(accl[u], a0, a1, a2, a3, b0, b1);
        }
    }

    #pragma unroll
    for (int u = 0; u < 8; ++u) {
        const int col = wn * 64 + u * 8 + tig * 2;
        const float bg0 = bgo[col], bg1 = bgo[col + 1];
        const float bl0 = blo[col], bl1 = blo[col + 1];
        const int row = r0 + wm * 16 + group;
        float v0 = sigmoidf_(accg[u][0] + bg0) * (accl[u][0] + bl0);
        float v1 = sigmoidf_(accg[u][1] + bg1) * (accl[u][1] + bl1);
        float v2 = sigmoidf_(accg[u][2] + bg0) * (accl[u][2] + bl0);
        float v3 = sigmoidf_(accg[u][3] + bg1) * (accl[u][3] + bl1);
        *(float2*)(out + (size_t)row * 128 + col)       = make_float2(v0, v1);
        *(float2*)(out + (size_t)(row + 8) * 128 + col) = make_float2(v2, v3);
    }
}

// ---------------------------------------------------------------------------
extern "C" void kernel_launch(void* const* d_in, const int* in_sizes, int n_in,
                              void* d_out, int out_size)
{
    const float* z    = (const float*)d_in[0];
    const float* lnw  = (const float*)d_in[1];
    const float* lnb  = (const float*)d_in[2];
    const float* Wga  = (const float*)d_in[3];
    const float* bga  = (const float*)d_in[4];
    const float* Wla  = (const float*)d_in[5];
    const float* bla  = (const float*)d_in[6];
    const float* Wgb  = (const float*)d_in[7];
    const float* bgb  = (const float*)d_in[8];
    const float* Wlb  = (const float*)d_in[9];
    const float* blb  = (const float*)d_in[10];
    const float* lnow = (const float*)d_in[11];
    const float* lnob = (const float*)d_in[12];
    const float* Wgo  = (const float*)d_in[13];
    const float* bgo  = (const float*)d_in[14];
    const float* Wlo  = (const float*)d_in[15];
    const float* blo  = (const float*)d_in[16];
    float* out = (float*)d_out;

    const size_t smem1 = (size_t)(128 * PAD + 2 * 128 * WSTR) * sizeof(float);  // 206848
    const size_t smemE = (size_t)(4 * ESTG) * sizeof(float);                    // 81920
    const size_t smem3 = (size_t)(3 * 128 * FPAD) * sizeof(float);              // 215040
    cudaFuncSetAttribute(k_proj_a,    cudaFuncAttributeMaxDynamicSharedMemorySize, (int)smem1);
    cudaFuncSetAttribute(k_proj_bt,   cudaFuncAttributeMaxDynamicSharedMemorySize, (int)smem1);
    cudaFuncSetAttribute(k_einsum_cp, cudaFuncAttributeMaxDynamicSharedMemorySize, (int)smemE);
    cudaFuncSetAttribute(k_final,     cudaFuncAttributeMaxDynamicSharedMemorySize, (int)smem3);

    k_proj_a <<<2048, 512, smem1>>>(z, lnw, lnb, Wga, bga, Wla, bla);
    k_proj_bt<<<2048, 512, smem1>>>(z, lnw, lnb, Wgb, bgb, Wlb, blb);
    k_einsum_cp<<<dim3(4, 4, 128), 256, smemE>>>();
    k_final<<<2048, 512, smem3>>>(z, lnw, lnb, lnow, lnob, Wgo, bgo, Wlo, blo, out);
}

// round 14
// speedup vs baseline: 1.1403x; 1.0116x over previous
#include <cuda_runtime.h>
#include <cstdint>

#define LQ 512
#define LLQ (512*512)
#define PAD 132    // proj: activation stride (4g+t clean)
#define WSTR 136   // universal stride: 8g+t (row) and 8t+g (col) both conflict-free

// scratch. g_a and g_bt have the K dim (m) PERMUTED within 8-blocks:
// pos = (m&~7) | ((m&3)<<1) | ((m>>2)&1)
__device__ float g_a [(size_t)128 * LLQ];   // a [c][i][perm(m)] (tf32)
__device__ float g_bt[(size_t)128 * LLQ];   // b^T [c][j][perm(m)] (tf32)
__device__ float g_k [(size_t)128 * LLQ];   // k [c][i][j]       (fp32, plain)

__device__ __forceinline__ float sigmoidf_(float x) {
    return 1.0f / (1.0f + __expf(-x));
}
__device__ __forceinline__ float to_tf32(float x) {
    uint32_t u;
    asm("cvt.rna.tf32.f32 %0, %1;" : "=r"(u) : "f"(x));
    return __uint_as_float(u);
}
__device__ __forceinline__ uint32_t smem_u32(const void* p) {
    uint32_t a;
    asm("{ .reg .u64 t; cvta.to.shared.u64 t, %1; cvt.u32.u64 %0, t; }" : "=r"(a) : "l"(p));
    return a;
}
__device__ __forceinline__ void mma_tf32(float* d, uint32_t a0, uint32_t a1, uint32_t a2, uint32_t a3,
                                         uint32_t b0, uint32_t b1) {
    asm volatile(
        "mma.sync.aligned.m16n8k8.row.col.f32.tf32.tf32.f32 "
        "{%0,%1,%2,%3}, {%4,%5,%6,%7}, {%8,%9}, {%0,%1,%2,%3};"
        : "+f"(d[0]), "+f"(d[1]), "+f"(d[2]), "+f"(d[3])
        : "r"(a0), "r"(a1), "r"(a2), "r"(a3), "r"(b0), "r"(b1));
}

#define CP_ASYNC16(dst, src) \
    asm volatile("cp.async.ca.shared.global [%0], [%1], 16;" :: "r"(dst), "l"(src) : "memory")
#define CP_COMMIT() asm volatile("cp.async.commit_group;" ::: "memory")
#define CP_WAIT1()  asm volatile("cp.async.wait_group 1;"  ::: "memory")
#define CP_WAIT0()  asm volatile("cp.async.wait_group 0;"  ::: "memory")

// ---------------------------------------------------------------------------
// Kernel 1a (R11): LN(z) + gated projection (a-pair) -> g_a [c][i][perm(m)]
// ---------------------------------------------------------------------------
__global__ void __launch_bounds__(512, 1) k_proj_a(
    const float* __restrict__ z,
    const float* __restrict__ lnw, const float* __restrict__ lnb,
    const float* __restrict__ Wg, const float* __restrict__ bg,
    const float* __restrict__ Wl, const float* __restrict__ bl)
{
    extern __shared__ float sm[];
    float* zn  = sm;                          // [128][PAD]
    float* Wt0 = sm + 128 * PAD;              // [128][WSTR]
    float* Wt1 = sm + 128 * PAD + 128 * WSTR; // [128][WSTR]

    const int tid  = threadIdx.x;
    const int r0   = blockIdx.x * 128;
    const int lane = tid & 31, warp = tid >> 5;
    const uint32_t sW0 = smem_u32(Wt0);
    const uint32_t sW1 = smem_u32(Wt1);

    #pragma unroll
    for (int it = 0; it < 8; ++it) {
        int idx = it * 512 + tid;
        int k = idx >> 5, q = idx & 31;
        uint32_t off = (uint32_t)(k * WSTR + q * 4) * 4u;
        CP_ASYNC16(sW0 + off, Wg + k * 128 + q * 4);
        CP_ASYNC16(sW1 + off, Wl + k * 128 + q * 4);
    }
    CP_COMMIT();

    {
        const float w0 = lnw[lane], w1 = lnw[lane + 32], w2 = lnw[lane + 64], w3 = lnw[lane + 96];
        const float c0 = lnb[lane], c1 = lnb[lane + 32], c2 = lnb[lane + 64], c3 = lnb[lane + 96];
        for (int it = 0; it < 8; ++it) {
            int row = warp * 8 + it;
            const float* zr = z + (size_t)(r0 + row) * 128;
            float x0 = zr[lane], x1 = zr[lane + 32], x2 = zr[lane + 64], x3 = zr[lane + 96];
            float s = x0 + x1 + x2 + x3;
            float q = x0 * x0 + x1 * x1 + x2 * x2 + x3 * x3;
            #pragma unroll
            for (int o = 16; o > 0; o >>= 1) {
                s += __shfl_xor_sync(0xffffffffu, s, o);
                q += __shfl_xor_sync(0xffffffffu, q, o);
            }
            float mu  = s * (1.0f / 128.0f);
            float var = q * (1.0f / 128.0f) - mu * mu;
            float rs  = rsqrtf(var + 1e-5f);
            float* zo = zn + row * PAD;
            zo[lane]      = to_tf32((x0 - mu) * rs * w0 + c0);
            zo[lane + 32] = to_tf32((x1 - mu) * rs * w1 + c1);
            zo[lane + 64] = to_tf32((x2 - mu) * rs * w2 + c2);
            zo[lane + 96] = to_tf32((x3 - mu) * rs * w3 + c3);
        }
    }

    CP_WAIT0();
    __syncthreads();
    #pragma unroll
    for (int it = 0; it < 8; ++it) {
        int idx = it * 512 + tid;
        int k = idx >> 5, q = idx & 31;
        float4* p0 = (float4*)(Wt0 + k * WSTR + q * 4);
        float4* p1 = (float4*)(Wt1 + k * WSTR + q * 4);
        float4 v0 = *p0, v1 = *p1;
        v0.x = to_tf32(v0.x); v0.y = to_tf32(v0.y); v0.z = to_tf32(v0.z); v0.w = to_tf32(v0.w);
        v1.x = to_tf32(v1.x); v1.y = to_tf32(v1.y); v1.z = to_tf32(v1.z); v1.w = to_tf32(v1.w);
        *p0 = v0; *p1 = v1;
    }
    __syncthreads();

    const int wm = warp >> 1, wn = warp & 1;
    const int group = lane >> 2, tig = lane & 3;
    const int arow0 = wm * 16 + group;
    const int brow0 = wn * 64 + group;
    const int pgrp  = ((group & 3) << 1) | (group >> 2);

    float accg[8][4], accl[8][4];
    #pragma unroll
    for (int u = 0; u < 8; ++u)
        #pragma unroll
        for (int v = 0; v < 4; ++v) { accg[u][v] = 0.0f; accl[u][v] = 0.0f; }

    #pragma unroll
    for (int ks = 0; ks < 16; ++ks) {
        const int k = ks * 8;
        uint32_t a0 = __float_as_uint(zn[arow0 * PAD + k + tig]);
        uint32_t a1 = __float_as_uint(zn[(arow0 + 8) * PAD + k + tig]);
        uint32_t a2 = __float_as_uint(zn[arow0 * PAD + k + tig + 4]);
        uint32_t a3 = __float_as_uint(zn[(arow0 + 8) * PAD + k + tig + 4]);
        #pragma unroll
        for (int u = 0; u < 8; ++u) {
            int rb = brow0 + u * 8;
            uint32_t b0 = __float_as_uint(Wt0[(k + tig) * WSTR + rb]);
            uint32_t b1 = __float_as_uint(Wt0[(k + tig + 4) * WSTR + rb]);
            mma_tf32(accg[u], a0, a1, a2, a3, b0, b1);
        }
    }
    #pragma unroll
    for (int ks = 0; ks < 16; ++ks) {
        const int k = ks * 8;
        uint32_t a0 = __float_as_uint(zn[arow0 * PAD + k + tig]);
        uint32_t a1 = __float_as_uint(zn[(arow0 + 8) * PAD + k + tig]);
        uint32_t a2 = __float_as_uint(zn[arow0 * PAD + k + tig + 4]);
        uint32_t a3 = __float_as_uint(zn[(arow0 + 8) * PAD + k + tig + 4]);
        #pragma unroll
        for (int u = 0; u < 8; ++u) {
            int rb = brow0 + u * 8;
            uint32_t b0 = __float_as_uint(Wt1[(k + tig) * WSTR + rb]);
            uint32_t b1 = __float_as_uint(Wt1[(k + tig + 4) * WSTR + rb]);
            mma_tf32(accl[u], a0, a1, a2, a3, b0, b1);
        }
    }

    const int rowp = r0 + wm * 16 + pgrp;
    #pragma unroll
    for (int u = 0; u < 8; ++u) {
        const int col = wn * 64 + u * 8 + tig * 2;
        const float bg0 = bg[col], bg1 = bg[col + 1];
        const float bl0 = bl[col], bl1 = bl[col + 1];
        float v0 = to_tf32(sigmoidf_(accg[u][0] + bg0) * (accl[u][0] + bl0));
        float v1 = to_tf32(sigmoidf_(accg[u][1] + bg1) * (accl[u][1] + bl1));
        float v2 = to_tf32(sigmoidf_(accg[u][2] + bg0) * (accl[u][2] + bl0));
        float v3 = to_tf32(sigmoidf_(accg[u][3] + bg1) * (accl[u][3] + bl1));
        g_a[(size_t)col       * LLQ + rowp]     = v0;
        g_a[(size_t)(col + 1) * LLQ + rowp]     = v1;
        g_a[(size_t)col       * LLQ + rowp + 8] = v2;
        g_a[(size_t)(col + 1) * LLQ + rowp + 8] = v3;
    }
}

// ---------------------------------------------------------------------------
// Kernel 1b (R11): LN(z) + gated projection (b-pair) -> g_bt [c][j][perm(m)]
// ---------------------------------------------------------------------------
__global__ void __launch_bounds__(512, 1) k_proj_bt(
    const float* __restrict__ z,
    const float* __restrict__ lnw, const float* __restrict__ lnb,
    const float* __restrict__ Wg, const float* __restrict__ bg,
    const float* __restrict__ Wl, const float* __restrict__ bl)
{
    extern __shared__ float sm[];
    float* zn  = sm;
    float* Wt0 = sm + 128 * PAD;
    float* Wt1 = sm + 128 * PAD + 128 * WSTR;

    const int tid  = threadIdx.x;
    const int m0   = (blockIdx.x & 3) * 128;
    const int j    = blockIdx.x >> 2;
    const int lane = tid & 31, warp = tid >> 5;
    const uint32_t sW0 = smem_u32(Wt0);
    const uint32_t sW1 = smem_u32(Wt1);

    #pragma unroll
    for (int it = 0; it < 8; ++it) {
        int idx = it * 512 + tid;
        int k = idx >> 5, q = idx & 31;
        uint32_t off = (uint32_t)(k * WSTR + q * 4) * 4u;
        CP_ASYNC16(sW0 + off, Wg + k * 128 + q * 4);
        CP_ASYNC16(sW1 + off, Wl + k * 128 + q * 4);
    }
    CP_COMMIT();

    {
        const float w0 = lnw[lane], w1 = lnw[lane + 32], w2 = lnw[lane + 64], w3 = lnw[lane + 96];
        const float c0 = lnb[lane], c1 = lnb[lane + 32], c2 = lnb[lane + 64], c3 = lnb[lane + 96];
        for (int it = 0; it < 8; ++it) {
            int row = warp * 8 + it;
            const float* zr = z + ((size_t)(m0 + row) * LQ + j) * 128;
            float x0 = zr[lane], x1 = zr[lane + 32], x2 = zr[lane + 64], x3 = zr[lane + 96];
            float s = x0 + x1 + x2 + x3;
            float q = x0 * x0 + x1 * x1 + x2 * x2 + x3 * x3;
            #pragma unroll
            for (int o = 16; o > 0; o >>= 1) {
                s += __shfl_xor_sync(0xffffffffu, s, o);
                q += __shfl_xor_sync(0xffffffffu, q, o);
            }
            float mu  = s * (1.0f / 128.0f);
            float var = q * (1.0f / 128.0f) - mu * mu;
            float rs  = rsqrtf(var + 1e-5f);
            float* zo = zn + row * PAD;
            zo[lane]      = to_tf32((x0 - mu) * rs * w0 + c0);
            zo[lane + 32] = to_tf32((x1 - mu) * rs * w1 + c1);
            zo[lane + 64] = to_tf32((x2 - mu) * rs * w2 + c2);
            zo[lane + 96] = to_tf32((x3 - mu) * rs * w3 + c3);
        }
    }

    CP_WAIT0();
    __syncthreads();
    #pragma unroll
    for (int it = 0; it < 8; ++it) {
        int idx = it * 512 + tid;
        int k = idx >> 5, q = idx & 31;
        float4* p0 = (float4*)(Wt0 + k * WSTR + q * 4);
        float4* p1 = (float4*)(Wt1 + k * WSTR + q * 4);
        float4 v0 = *p0, v1 = *p1;
        v0.x = to_tf32(v0.x); v0.y = to_tf32(v0.y); v0.z = to_tf32(v0.z); v0.w = to_tf32(v0.w);
        v1.x = to_tf32(v1.x); v1.y = to_tf32(v1.y); v1.z = to_tf32(v1.z); v1.w = to_tf32(v1.w);
        *p0 = v0; *p1 = v1;
    }
    __syncthreads();

    const int wm = warp >> 1, wn = warp & 1;
    const int group = lane >> 2, tig = lane & 3;
    const int arow0 = wm * 16 + group;
    const int brow0 = wn * 64 + group;
    const int pgrp  = ((group & 3) << 1) | (group >> 2);

    float accg[8][4], accl[8][4];
    #pragma unroll
    for (int u = 0; u < 8; ++u)
        #pragma unroll
        for (int v = 0; v < 4; ++v) { accg[u][v] = 0.0f; accl[u][v] = 0.0f; }

    #pragma unroll
    for (int ks = 0; ks < 16; ++ks) {
        const int k = ks * 8;
        uint32_t a0 = __float_as_uint(zn[arow0 * PAD + k + tig]);
        uint32_t a1 = __float_as_uint(zn[(arow0 + 8) * PAD + k + tig]);
        uint32_t a2 = __float_as_uint(zn[arow0 * PAD + k + tig + 4]);
        uint32_t a3 = __float_as_uint(zn[(arow0 + 8) * PAD + k + tig + 4]);
        #pragma unroll
        for (int u = 0; u < 8; ++u) {
            int rb = brow0 + u * 8;
            uint32_t b0 = __float_as_uint(Wt0[(k + tig) * WSTR + rb]);
            uint32_t b1 = __float_as_uint(Wt0[(k + tig + 4) * WSTR + rb]);
            mma_tf32(accg[u], a0, a1, a2, a3, b0, b1);
        }
    }
    #pragma unroll
    for (int ks = 0; ks < 16; ++ks) {
        const int k = ks * 8;
        uint32_t a0 = __float_as_uint(zn[arow0 * PAD + k + tig]);
        uint32_t a1 = __float_as_uint(zn[(arow0 + 8) * PAD + k + tig]);
        uint32_t a2 = __float_as_uint(zn[arow0 * PAD + k + tig + 4]);
        uint32_t a3 = __float_as_uint(zn[(arow0 + 8) * PAD + k + tig + 4]);
        #pragma unroll
        for (int u = 0; u < 8; ++u) {
            int rb = brow0 + u * 8;
            uint32_t b0 = __float_as_uint(Wt1[(k + tig) * WSTR + rb]);
            uint32_t b1 = __float_as_uint(Wt1[(k + tig + 4) * WSTR + rb]);
            mma_tf32(accl[u], a0, a1, a2, a3, b0, b1);
        }
    }

    const int mp = m0 + wm * 16 + pgrp;
    float* dst = g_bt + (size_t)j * LQ + mp;
    #pragma unroll
    for (int u = 0; u < 8; ++u) {
        const int col = wn * 64 + u * 8 + tig * 2;
        const float bg0 = bg[col], bg1 = bg[col + 1];
        const float bl0 = bl[col], bl1 = bl[col + 1];
        float v0 = to_tf32(sigmoidf_(accg[u][0] + bg0) * (accl[u][0] + bl0));
        float v1 = to_tf32(sigmoidf_(accg[u][1] + bg1) * (accl[u][1] + bl1));
        float v2 = to_tf32(sigmoidf_(accg[u][2] + bg0) * (accl[u][2] + bl0));
        float v3 = to_tf32(sigmoidf_(accg[u][3] + bg1) * (accl[u][3] + bl1));
        dst[(size_t)col       * LLQ]     = v0;
        dst[(size_t)(col + 1) * LLQ]     = v1;
        dst[(size_t)col       * LLQ + 8] = v2;
        dst[(size_t)(col + 1) * LLQ + 8] = v3;
    }
}

// ---------------------------------------------------------------------------
// Kernel 2 (R11): 2-stage cp.async mma.sync TF32 einsum, permuted-K, EPAD 40.
// ---------------------------------------------------------------------------
#define EPAD 40
#define ESTG (128 * EPAD)

__global__ void __launch_bounds__(256, 2) k_einsum_cp()
{
    extern __shared__ float es[];
    float* As = es;
    float* Bs = es + 2 * ESTG;

    const int tid  = threadIdx.x;
    const int lane = tid & 31, warp = tid >> 5;
    const int wm = warp & 3;
    const int wn = warp >> 2;
    const int c  = blockIdx.z;
    const int i0 = blockIdx.y * 128;
    const int j0 = blockIdx.x * 128;

    const float* A  = g_a  + (size_t)c * LLQ;
    const float* Bt = g_bt + (size_t)c * LLQ;

    const uint32_t sA = smem_u32(As);
    const uint32_t sB = smem_u32(Bs);

    int lrow[4], lq[4];
    #pragma unroll
    for (int r = 0; r < 4; ++r) {
        int idx = r * 256 + tid;
        lrow[r] = idx >> 3;
        lq[r]   = idx & 7;
    }

    #pragma unroll
    for (int kt = 0; kt < 2; ++kt) {
        #pragma unroll
        for (int r = 0; r < 4; ++r) {
            uint32_t off = (uint32_t)(kt * ESTG + lrow[r] * EPAD + lq[r] * 4) * 4u;
            CP_ASYNC16(sA + off, A  + (size_t)(i0 + lrow[r]) * LQ + kt * 32 + lq[r] * 4);
            CP_ASYNC16(sB + off, Bt + (size_t)(j0 + lrow[r]) * LQ + kt * 32 + lq[r] * 4);
        }
        CP_COMMIT();
    }

    float acc[2][8][4];
    #pragma unroll
    for (int t = 0; t < 2; ++t)
        #pragma unroll
        for (int u = 0; u < 8; ++u)
            #pragma unroll
            for (int v = 0; v < 4; ++v) acc[t][u][v] = 0.0f;

    const int arow0 = wm * 32 + (lane >> 2);
    const int tig2  = (lane & 3) * 2;
    const int brow0 = wn * 64 + (lane >> 2);

    #pragma unroll 1
    for (int kt = 0; kt < 16; ++kt) {
        const int buf = kt & 1;
        if (kt < 14) { CP_WAIT1(); } else { CP_WAIT0(); }
        __syncthreads();

        const float* Ab = As + buf * ESTG;
        const float* Bb = Bs + buf * ESTG;

        #pragma unroll
        for (int ks = 0; ks < 4; ++ks) {
            const int fo = ks * 8 + tig2;
            uint32_t af[2][4];
            #pragma unroll
            for (int t = 0; t < 2; ++t) {
                int ra = arow0 + t * 16;
                float2 fa0 = *(const float2*)(Ab + ra * EPAD + fo);
                float2 fa1 = *(const float2*)(Ab + (ra + 8) * EPAD + fo);
                af[t][0] = __float_as_uint(fa0.x); af[t][2] = __float_as_uint(fa0.y);
                af[t][1] = __float_as_uint(fa1.x); af[t][3] = __float_as_uint(fa1.y);
            }
            #pragma unroll
            for (int u = 0; u < 8; ++u) {
                int rb = brow0 + u * 8;
                float2 fb = *(const float2*)(Bb + rb * EPAD + fo);
                uint32_t b0 = __float_as_uint(fb.x), b1 = __float_as_uint(fb.y);
                mma_tf32(acc[0][u], af[0][0], af[0][1], af[0][2], af[0][3], b0, b1);
                mma_tf32(acc[1][u], af[1][0], af[1][1], af[1][2], af[1][3], b0, b1);
            }
        }
        __syncthreads();

        if (kt + 2 < 16) {
            const int nk = kt + 2;
            #pragma unroll
            for (int r = 0; r < 4; ++r) {
                uint32_t off = (uint32_t)(buf * ESTG + lrow[r] * EPAD + lq[r] * 4) * 4u;
                CP_ASYNC16(sA + off, A  + (size_t)(i0 + lrow[r]) * LQ + nk * 32 + lq[r] * 4);
                CP_ASYNC16(sB + off, Bt + (size_t)(j0 + lrow[r]) * LQ + nk * 32 + lq[r] * 4);
            }
            CP_COMMIT();
        }
    }

    float* K = g_k + (size_t)c * LLQ;
    const int orow = i0 + wm * 32 + (lane >> 2);
    const int ocol = j0 + wn * 64 + (lane & 3) * 2;
    #pragma unroll
    for (int t = 0; t < 2; ++t) {
        #pragma unroll
        for (int u = 0; u < 8; ++u) {
            float* p0 = K + (size_t)(orow + t * 16)     * LQ + ocol + u * 8;
            float* p1 = K + (size_t)(orow + t * 16 + 8) * LQ + ocol + u * 8;
            *(float2*)p0 = make_float2(acc[t][u][0], acc[t][u][1]);
            *(float2*)p1 = make_float2(acc[t][u][2], acc[t][u][3]);
        }
    }
}

// ---------------------------------------------------------------------------
// Kernel 3: out = sigmoid(LN(z)@Wgo + bgo) * (LN(k)@Wlo + blo)
// kn stored CHANNEL-MAJOR in smem (kn[c][jl], stride WSTR): gather uses 16B
// cp.async issued at kernel entry (overlaps LN(z) + gate GEMM); linear-GEMM
// A-frags read column-wise (8t+g pattern, conflict-free). All strides 136.
// ---------------------------------------------------------------------------
__global__ void __launch_bounds__(512, 1) k_final(
    const float* __restrict__ z,
    const float* __restrict__ lnw, const float* __restrict__ lnb,
    const float* __restrict__ lnow, const float* __restrict__ lnob,
    const float* __restrict__ Wgo, const float* __restrict__ bgo,
    const float* __restrict__ Wlo, const float* __restrict__ blo,
    float* __restrict__ out)
{
    extern __shared__ float sm[];
    float* zn  = sm;                   // [128][WSTR]  LN(z)
    float* Wt0 = sm + 128 * WSTR;      // [128][WSTR]  Wgo (k rows)
    float* kn  = sm + 2 * 128 * WSTR;  // [128][WSTR]  kn CHANNEL-major: kn[c][jl]
    // Wlo reuses zn region after gate GEMM? No — keep it simple: Wlo loaded
    // into Wt0 after gate GEMM (Wt0 free then). Only 3 buffers needed.

    const int tid  = threadIdx.x;
    const int r0   = blockIdx.x * 128;
    const int i    = r0 >> 9;
    const int j0   = r0 & 511;
    const int lane = tid & 31, warp = tid >> 5;

    const uint32_t sW0 = smem_u32(Wt0);
    const uint32_t sKn = smem_u32(kn);

    // group0: Wgo
    #pragma unroll
    for (int it = 0; it < 8; ++it) {
        int idx = it * 512 + tid;
        int k = idx >> 5, q = idx & 31;
        CP_ASYNC16(sW0 + (uint32_t)(k * WSTR + q * 4) * 4u, Wgo + k * 128 + q * 4);
    }
    CP_COMMIT();
    // group1: kn gather, channel-major, 16B chunks (overlaps LN(z)+gate GEMM)
    #pragma unroll
    for (int it = 0; it < 8; ++it) {
        int idx = it * 512 + tid;
        int c = idx >> 5, q = idx & 31;   // q*4 = jl offset
        CP_ASYNC16(sKn + (uint32_t)(c * WSTR + q * 4) * 4u,
                   g_k + (size_t)c * LLQ + (size_t)i * LQ + j0 + q * 4);
    }
    CP_COMMIT();

    // LN(z) -> zn (stride WSTR; 8g+t row pattern conflict-free)
    {
        const float w0 = lnw[lane], w1 = lnw[lane + 32], w2 = lnw[lane + 64], w3 = lnw[lane + 96];
        const float c0 = lnb[lane], c1 = lnb[lane + 32], c2 = lnb[lane + 64], c3 = lnb[lane + 96];
        for (int it = 0; it < 8; ++it) {
            int row = warp * 8 + it;
            const float* zr = z + (size_t)(r0 + row) * 128;
            float x0 = zr[lane], x1 = zr[lane + 32], x2 = zr[lane + 64], x3 = zr[lane + 96];
            float s = x0 + x1 + x2 + x3;
            float q = x0 * x0 + x1 * x1 + x2 * x2 + x3 * x3;
            #pragma unroll
            for (int o = 16; o > 0; o >>= 1) {
                s += __shfl_xor_sync(0xffffffffu, s, o);
                q += __shfl_xor_sync(0xffffffffu, q, o);
            }
            float mu  = s * (1.0f / 128.0f);
            float var = q * (1.0f / 128.0f) - mu * mu;
            float rs  = rsqrtf(var + 1e-5f);
            float* zo = zn + row * WSTR;
            zo[lane]      = to_tf32((x0 - mu) * rs * w0 + c0);
            zo[lane + 32] = to_tf32((x1 - mu) * rs * w1 + c1);
            zo[lane + 64] = to_tf32((x2 - mu) * rs * w2 + c2);
            zo[lane + 96] = to_tf32((x3 - mu) * rs * w3 + c3);
        }
    }

    CP_WAIT1();      // Wgo (group0) complete; gather may still be in flight
    __syncthreads();
    // round Wgo in place
    #pragma unroll
    for (int it = 0; it < 8; ++it) {
        int idx = it * 512 + tid;
        int k = idx >> 5, q = idx & 31;
        float4* p0 = (float4*)(Wt0 + k * WSTR + q * 4);
        float4 v0 = *p0;
        v0.x = to_tf32(v0.x); v0.y = to_tf32(v0.y); v0.z = to_tf32(v0.z); v0.w = to_tf32(v0.w);
        *p0 = v0;
    }
    __syncthreads();

    const int wm = warp >> 1, wn = warp & 1;
    const int group = lane >> 2, tig = lane & 3;
    const int arow0 = wm * 16 + group;
    const int brow0 = wn * 64 + group;

    // gate GEMM: zn x Wgo
    float accg[8][4];
    #pragma unroll
    for (int u = 0; u < 8; ++u)
        #pragma unroll
        for (int v = 0; v < 4; ++v) accg[u][v] = 0.0f;

    #pragma unroll
    for (int ks = 0; ks < 16; ++ks) {
        const int k = ks * 8;
        uint32_t a0 = __float_as_uint(zn[arow0 * WSTR + k + tig]);
        uint32_t a1 = __float_as_uint(zn[(arow0 + 8) * WSTR + k + tig]);
        uint32_t a2 = __float_as_uint(zn[arow0 * WSTR + k + tig + 4]);
        uint32_t a3 = __float_as_uint(zn[(arow0 + 8) * WSTR + k + tig + 4]);
        #pragma unroll
        for (int u = 0; u < 8; ++u) {
            int rb = brow0 + u * 8;
            uint32_t b0 = __float_as_uint(Wt0[(k + tig) * WSTR + rb]);
            uint32_t b1 = __float_as_uint(Wt0[(k + tig + 4) * WSTR + rb]);
            mma_tf32(accg[u], a0, a1, a2, a3, b0, b1);
        }
    }
    __syncthreads();   // Wt0 reads done -> free for Wlo

    // group2: Wlo -> Wt0 (overlaps LN(k))
    #pragma unroll
    for (int it = 0; it < 8; ++it) {
        int idx = it * 512 + tid;
        int k = idx >> 5, q = idx & 31;
        CP_ASYNC16(sW0 + (uint32_t)(k * WSTR + q * 4) * 4u, Wlo + k * 128 + q * 4);
    }
    CP_COMMIT();

    CP_WAIT1();       // kn gather (group1) complete; Wlo (group2) in flight
    __syncthreads();

    // LN(k): stats over c for each jl. kn is channel-major: x_c = kn[c][jl].
    // Column access (8-way bank conflicts) but tiny volume.
    {
        const float w0 = lnow[lane], w1 = lnow[lane + 32], w2 = lnow[lane + 64], w3 = lnow[lane + 96];
        const float c0 = lnob[lane], c1 = lnob[lane + 32], c2 = lnob[lane + 64], c3 = lnob[lane + 96];
        for (int it = 0; it < 8; ++it) {
            int jl = warp * 8 + it;
            float x0 = kn[(size_t)lane * WSTR + jl];
            float x1 = kn[(size_t)(lane + 32) * WSTR + jl];
            float x2 = kn[(size_t)(lane + 64) * WSTR + jl];
            float x3 = kn[(size_t)(lane + 96) * WSTR + jl];
            float s = x0 + x1 + x2 + x3;
            float q = x0 * x0 + x1 * x1 + x2 * x2 + x3 * x3;
            #pragma unroll
            for (int o = 16; o > 0; o >>= 1) {
                s += __shfl_xor_sync(0xffffffffu, s, o);
                q += __shfl_xor_sync(0xffffffffu, q, o);
            }
            float mu  = s * (1.0f / 128.0f);
            float var = q * (1.0f / 128.0f) - mu * mu;
            float rs  = rsqrtf(var + 1e-5f);
            kn[(size_t)lane * WSTR + jl]        = to_tf32((x0 - mu) * rs * w0 + c0);
            kn[(size_t)(lane + 32) * WSTR + jl] = to_tf32((x1 - mu) * rs * w1 + c1);
            kn[(size_t)(lane + 64) * WSTR + jl] = to_tf32((x2 - mu) * rs * w2 + c2);
            kn[(size_t)(lane + 96) * WSTR + jl] = to_tf32((x3 - mu) * rs * w3 + c3);
        }
    }

    CP_WAIT0();       // Wlo arrived
    __syncthreads();
    // round Wlo in place
    #pragma unroll
    for (int it = 0; it < 8; ++it) {
        int idx = it * 512 + tid;
        int k = idx >> 5, q = idx & 31;
        float4* p0 = (float4*)(Wt0 + k * WSTR + q * 4);
        float4 v0 = *p0;
        v0.x = to_tf32(v0.x); v0.y = to_tf32(v0.y); v0.z = to_tf32(v0.z); v0.w = to_tf32(v0.w);
        *p0 = v0;
    }
    __syncthreads();

    // linear GEMM: A = kn^T (logical [jl][c], stored [c][jl]) x Wlo
    // A-frag: a0 = A[arow0][k+tig] = kn[(k+tig)][arow0]  (8t+g, conflict-free)
    float accl[8][4];
    #pragma unroll
    for (int u = 0; u < 8; ++u)
        #pragma unroll
        for (int v = 0; v < 4; ++v) accl[u][v] = 0.0f;

    #pragma unroll
    for (int ks = 0; ks < 16; ++ks) {
        const int k = ks * 8;
        uint32_t a0 = __float_as_uint(kn[(k + tig) * WSTR + arow0]);
        uint32_t a1 = __float_as_uint(kn[(k + tig) * WSTR + arow0 + 8]);
        uint32_t a2 = __float_as_uint(kn[(k + tig + 4) * WSTR + arow0]);
        uint32_t a3 = __float_as_uint(kn[(k + tig + 4) * WSTR + arow0 + 8]);
        #pragma unroll
        for (int u = 0; u < 8; ++u) {
            int rb = brow0 + u * 8;
            uint32_t b0 = __float_as_uint(Wt0[(k + tig) * WSTR + rb]);
            uint32_t b1 = __float_as_uint(Wt0[(k + tig + 4) * WSTR + rb]);
            mma_tf32(accl[u], a0, a1, a2, a3, b0, b1);
        }
    }

    #pragma unroll
    for (int u = 0; u < 8; ++u) {
        const int col = wn * 64 + u * 8 + tig * 2;
        const float bg0 = bgo[col], bg1 = bgo[col + 1];
        const float bl0 = blo[col], bl1 = blo[col + 1];
        const int row = r0 + wm * 16 + group;
        float v0 = sigmoidf_(accg[u][0] + bg0) * (accl[u][0] + bl0);
        float v1 = sigmoidf_(accg[u][1] + bg1) * (accl[u][1] + bl1);
        float v2 = sigmoidf_(accg[u][2] + bg0) * (accl[u][2] + bl0);
        float v3 = sigmoidf_(accg[u][3] + bg1) * (accl[u][3] + bl1);
        *(float2*)(out + (size_t)row * 128 + col)       = make_float2(v0, v1);
        *(float2*)(out + (size_t)(row + 8) * 128 + col) = make_float2(v2, v3);
    }
}

// ---------------------------------------------------------------------------
extern "C" void kernel_launch(void* const* d_in, const int* in_sizes, int n_in,
                              void* d_out, int out_size)
{
    const float* z    = (const float*)d_in[0];
    const float* lnw  = (const float*)d_in[1];
    const float* lnb  = (const float*)d_in[2];
    const float* Wga  = (const float*)d_in[3];
    const float* bga  = (const float*)d_in[4];
    const float* Wla  = (const float*)d_in[5];
    const float* bla  = (const float*)d_in[6];
    const float* Wgb  = (const float*)d_in[7];
    const float* bgb  = (const float*)d_in[8];
    const float* Wlb  = (const float*)d_in[9];
    const float* blb  = (const float*)d_in[10];
    const float* lnow = (const float*)d_in[11];
    const float* lnob = (const float*)d_in[12];
    const float* Wgo  = (const float*)d_in[13];
    const float* bgo  = (const float*)d_in[14];
    const float* Wlo  = (const float*)d_in[15];
    const float* blo  = (const float*)d_in[16];
    float* out = (float*)d_out;

    const size_t smem1 = (size_t)(128 * PAD + 2 * 128 * WSTR) * sizeof(float);  // 206848
    const size_t smemE = (size_t)(4 * ESTG) * sizeof(float);                    // 81920
    const size_t smem3 = (size_t)(3 * 128 * WSTR) * sizeof(float);              // 208896
    cudaFuncSetAttribute(k_proj_a,    cudaFuncAttributeMaxDynamicSharedMemorySize, (int)smem1);
    cudaFuncSetAttribute(k_proj_bt,   cudaFuncAttributeMaxDynamicSharedMemorySize, (int)smem1);
    cudaFuncSetAttribute(k_einsum_cp, cudaFuncAttributeMaxDynamicSharedMemorySize, (int)smemE);
    cudaFuncSetAttribute(k_final,     cudaFuncAttributeMaxDynamicSharedMemorySize, (int)smem3);

    k_proj_a <<<2048, 512, smem1>>>(z, lnw, lnb, Wga, bga, Wla, bla);
    k_proj_bt<<<2048, 512, smem1>>>(z, lnw, lnb, Wgb, bgb, Wlb, blb);
    k_einsum_cp<<<dim3(4, 4, 128), 256, smemE>>>();
    k_final<<<2048, 512, smem3>>>(z, lnw, lnb, lnow, lnob, Wgo, bgo, Wlo, blo, out);
}

// round 15
// speedup vs baseline: 1.1598x; 1.0171x over previous
#include <cuda_runtime.h>
#include <cstdint>

#define LQ 512
#define LLQ (512*512)
#define PAD 132    // activation stride (4g+t clean)
#define WSTR 136   // weight stride (8t+g clean)

// scratch. g_a and g_bt have the K dim (m) PERMUTED within 8-blocks:
// pos = (m&~7) | ((m&3)<<1) | ((m>>2)&1)
__device__ float g_a [(size_t)128 * LLQ];   // a [c][i][perm(m)] (tf32)
__device__ float g_bt[(size_t)128 * LLQ];   // b^T [c][j][perm(m)] (tf32)
__device__ float g_k [(size_t)128 * LLQ];   // k [c][i][j]       (fp32, plain)

__device__ __forceinline__ float sigmoidf_(float x) {
    return 1.0f / (1.0f + __expf(-x));
}
__device__ __forceinline__ float to_tf32(float x) {
    uint32_t u;
    asm("cvt.rna.tf32.f32 %0, %1;" : "=r"(u) : "f"(x));
    return __uint_as_float(u);
}
__device__ __forceinline__ uint32_t smem_u32(const void* p) {
    uint32_t a;
    asm("{ .reg .u64 t; cvta.to.shared.u64 t, %1; cvt.u32.u64 %0, t; }" : "=r"(a) : "l"(p));
    return a;
}
__device__ __forceinline__ void mma_tf32(float* d, uint32_t a0, uint32_t a1, uint32_t a2, uint32_t a3,
                                         uint32_t b0, uint32_t b1) {
    asm volatile(
        "mma.sync.aligned.m16n8k8.row.col.f32.tf32.tf32.f32 "
        "{%0,%1,%2,%3}, {%4,%5,%6,%7}, {%8,%9}, {%0,%1,%2,%3};"
        : "+f"(d[0]), "+f"(d[1]), "+f"(d[2]), "+f"(d[3])
        : "r"(a0), "r"(a1), "r"(a2), "r"(a3), "r"(b0), "r"(b1));
}

#define CP_ASYNC16(dst, src) \
    asm volatile("cp.async.ca.shared.global [%0], [%1], 16;" :: "r"(dst), "l"(src) : "memory")
#define CP_ASYNC4(dst, src) \
    asm volatile("cp.async.ca.shared.global [%0], [%1], 4;"  :: "r"(dst), "l"(src) : "memory")
#define CP_COMMIT() asm volatile("cp.async.commit_group;" ::: "memory")
#define CP_WAIT1()  asm volatile("cp.async.wait_group 1;"  ::: "memory")
#define CP_WAIT0()  asm volatile("cp.async.wait_group 0;"  ::: "memory")

// ---------------------------------------------------------------------------
// Kernel 1a (R11): LN(z) + gated projection (a-pair) -> g_a [c][i][perm(m)]
// ---------------------------------------------------------------------------
__global__ void __launch_bounds__(512, 1) k_proj_a(
    const float* __restrict__ z,
    const float* __restrict__ lnw, const float* __restrict__ lnb,
    const float* __restrict__ Wg, const float* __restrict__ bg,
    const float* __restrict__ Wl, const float* __restrict__ bl)
{
    extern __shared__ float sm[];
    float* zn  = sm;                          // [128][PAD]
    float* Wt0 = sm + 128 * PAD;              // [128][WSTR]
    float* Wt1 = sm + 128 * PAD + 128 * WSTR; // [128][WSTR]

    const int tid  = threadIdx.x;
    const int r0   = blockIdx.x * 128;
    const int lane = tid & 31, warp = tid >> 5;
    const uint32_t sW0 = smem_u32(Wt0);
    const uint32_t sW1 = smem_u32(Wt1);

    #pragma unroll
    for (int it = 0; it < 8; ++it) {
        int idx = it * 512 + tid;
        int k = idx >> 5, q = idx & 31;
        uint32_t off = (uint32_t)(k * WSTR + q * 4) * 4u;
        CP_ASYNC16(sW0 + off, Wg + k * 128 + q * 4);
        CP_ASYNC16(sW1 + off, Wl + k * 128 + q * 4);
    }
    CP_COMMIT();

    {
        const float w0 = lnw[lane], w1 = lnw[lane + 32], w2 = lnw[lane + 64], w3 = lnw[lane + 96];
        const float c0 = lnb[lane], c1 = lnb[lane + 32], c2 = lnb[lane + 64], c3 = lnb[lane + 96];
        for (int it = 0; it < 8; ++it) {
            int row = warp * 8 + it;
            const float* zr = z + (size_t)(r0 + row) * 128;
            float x0 = zr[lane], x1 = zr[lane + 32], x2 = zr[lane + 64], x3 = zr[lane + 96];
            float s = x0 + x1 + x2 + x3;
            float q = x0 * x0 + x1 * x1 + x2 * x2 + x3 * x3;
            #pragma unroll
            for (int o = 16; o > 0; o >>= 1) {
                s += __shfl_xor_sync(0xffffffffu, s, o);
                q += __shfl_xor_sync(0xffffffffu, q, o);
            }
            float mu  = s * (1.0f / 128.0f);
            float var = q * (1.0f / 128.0f) - mu * mu;
            float rs  = rsqrtf(var + 1e-5f);
            float* zo = zn + row * PAD;
            zo[lane]      = to_tf32((x0 - mu) * rs * w0 + c0);
            zo[lane + 32] = to_tf32((x1 - mu) * rs * w1 + c1);
            zo[lane + 64] = to_tf32((x2 - mu) * rs * w2 + c2);
            zo[lane + 96] = to_tf32((x3 - mu) * rs * w3 + c3);
        }
    }

    CP_WAIT0();
    __syncthreads();
    #pragma unroll
    for (int it = 0; it < 8; ++it) {
        int idx = it * 512 + tid;
        int k = idx >> 5, q = idx & 31;
        float4* p0 = (float4*)(Wt0 + k * WSTR + q * 4);
        float4* p1 = (float4*)(Wt1 + k * WSTR + q * 4);
        float4 v0 = *p0, v1 = *p1;
        v0.x = to_tf32(v0.x); v0.y = to_tf32(v0.y); v0.z = to_tf32(v0.z); v0.w = to_tf32(v0.w);
        v1.x = to_tf32(v1.x); v1.y = to_tf32(v1.y); v1.z = to_tf32(v1.z); v1.w = to_tf32(v1.w);
        *p0 = v0; *p1 = v1;
    }
    __syncthreads();

    const int wm = warp >> 1, wn = warp & 1;
    const int group = lane >> 2, tig = lane & 3;
    const int arow0 = wm * 16 + group;
    const int brow0 = wn * 64 + group;
    const int pgrp  = ((group & 3) << 1) | (group >> 2);

    float accg[8][4], accl[8][4];
    #pragma unroll
    for (int u = 0; u < 8; ++u)
        #pragma unroll
        for (int v = 0; v < 4; ++v) { accg[u][v] = 0.0f; accl[u][v] = 0.0f; }

    #pragma unroll
    for (int ks = 0; ks < 16; ++ks) {
        const int k = ks * 8;
        uint32_t a0 = __float_as_uint(zn[arow0 * PAD + k + tig]);
        uint32_t a1 = __float_as_uint(zn[(arow0 + 8) * PAD + k + tig]);
        uint32_t a2 = __float_as_uint(zn[arow0 * PAD + k + tig + 4]);
        uint32_t a3 = __float_as_uint(zn[(arow0 + 8) * PAD + k + tig + 4]);
        #pragma unroll
        for (int u = 0; u < 8; ++u) {
            int rb = brow0 + u * 8;
            uint32_t b0 = __float_as_uint(Wt0[(k + tig) * WSTR + rb]);
            uint32_t b1 = __float_as_uint(Wt0[(k + tig + 4) * WSTR + rb]);
            mma_tf32(accg[u], a0, a1, a2, a3, b0, b1);
        }
    }
    #pragma unroll
    for (int ks = 0; ks < 16; ++ks) {
        const int k = ks * 8;
        uint32_t a0 = __float_as_uint(zn[arow0 * PAD + k + tig]);
        uint32_t a1 = __float_as_uint(zn[(arow0 + 8) * PAD + k + tig]);
        uint32_t a2 = __float_as_uint(zn[arow0 * PAD + k + tig + 4]);
        uint32_t a3 = __float_as_uint(zn[(arow0 + 8) * PAD + k + tig + 4]);
        #pragma unroll
        for (int u = 0; u < 8; ++u) {
            int rb = brow0 + u * 8;
            uint32_t b0 = __float_as_uint(Wt1[(k + tig) * WSTR + rb]);
            uint32_t b1 = __float_as_uint(Wt1[(k + tig + 4) * WSTR + rb]);
            mma_tf32(accl[u], a0, a1, a2, a3, b0, b1);
        }
    }

    const int rowp = r0 + wm * 16 + pgrp;
    #pragma unroll
    for (int u = 0; u < 8; ++u) {
        const int col = wn * 64 + u * 8 + tig * 2;
        const float bg0 = bg[col], bg1 = bg[col + 1];
        const float bl0 = bl[col], bl1 = bl[col + 1];
        float v0 = to_tf32(sigmoidf_(accg[u][0] + bg0) * (accl[u][0] + bl0));
        float v1 = to_tf32(sigmoidf_(accg[u][1] + bg1) * (accl[u][1] + bl1));
        float v2 = to_tf32(sigmoidf_(accg[u][2] + bg0) * (accl[u][2] + bl0));
        float v3 = to_tf32(sigmoidf_(accg[u][3] + bg1) * (accl[u][3] + bl1));
        g_a[(size_t)col       * LLQ + rowp]     = v0;
        g_a[(size_t)(col + 1) * LLQ + rowp]     = v1;
        g_a[(size_t)col       * LLQ + rowp + 8] = v2;
        g_a[(size_t)(col + 1) * LLQ + rowp + 8] = v3;
    }
}

// ---------------------------------------------------------------------------
// Kernel 1b (R11): LN(z) + gated projection (b-pair) -> g_bt [c][j][perm(m)]
// ---------------------------------------------------------------------------
__global__ void __launch_bounds__(512, 1) k_proj_bt(
    const float* __restrict__ z,
    const float* __restrict__ lnw, const float* __restrict__ lnb,
    const float* __restrict__ Wg, const float* __restrict__ bg,
    const float* __restrict__ Wl, const float* __restrict__ bl)
{
    extern __shared__ float sm[];
    float* zn  = sm;
    float* Wt0 = sm + 128 * PAD;
    float* Wt1 = sm + 128 * PAD + 128 * WSTR;

    const int tid  = threadIdx.x;
    const int m0   = (blockIdx.x & 3) * 128;
    const int j    = blockIdx.x >> 2;
    const int lane = tid & 31, warp = tid >> 5;
    const uint32_t sW0 = smem_u32(Wt0);
    const uint32_t sW1 = smem_u32(Wt1);

    #pragma unroll
    for (int it = 0; it < 8; ++it) {
        int idx = it * 512 + tid;
        int k = idx >> 5, q = idx & 31;
        uint32_t off = (uint32_t)(k * WSTR + q * 4) * 4u;
        CP_ASYNC16(sW0 + off, Wg + k * 128 + q * 4);
        CP_ASYNC16(sW1 + off, Wl + k * 128 + q * 4);
    }
    CP_COMMIT();

    {
        const float w0 = lnw[lane], w1 = lnw[lane + 32], w2 = lnw[lane + 64], w3 = lnw[lane + 96];
        const float c0 = lnb[lane], c1 = lnb[lane + 32], c2 = lnb[lane + 64], c3 = lnb[lane + 96];
        for (int it = 0; it < 8; ++it) {
            int row = warp * 8 + it;
            const float* zr = z + ((size_t)(m0 + row) * LQ + j) * 128;
            float x0 = zr[lane], x1 = zr[lane + 32], x2 = zr[lane + 64], x3 = zr[lane + 96];
            float s = x0 + x1 + x2 + x3;
            float q = x0 * x0 + x1 * x1 + x2 * x2 + x3 * x3;
            #pragma unroll
            for (int o = 16; o > 0; o >>= 1) {
                s += __shfl_xor_sync(0xffffffffu, s, o);
                q += __shfl_xor_sync(0xffffffffu, q, o);
            }
            float mu  = s * (1.0f / 128.0f);
            float var = q * (1.0f / 128.0f) - mu * mu;
            float rs  = rsqrtf(var + 1e-5f);
            float* zo = zn + row * PAD;
            zo[lane]      = to_tf32((x0 - mu) * rs * w0 + c0);
            zo[lane + 32] = to_tf32((x1 - mu) * rs * w1 + c1);
            zo[lane + 64] = to_tf32((x2 - mu) * rs * w2 + c2);
            zo[lane + 96] = to_tf32((x3 - mu) * rs * w3 + c3);
        }
    }

    CP_WAIT0();
    __syncthreads();
    #pragma unroll
    for (int it = 0; it < 8; ++it) {
        int idx = it * 512 + tid;
        int k = idx >> 5, q = idx & 31;
        float4* p0 = (float4*)(Wt0 + k * WSTR + q * 4);
        float4* p1 = (float4*)(Wt1 + k * WSTR + q * 4);
        float4 v0 = *p0, v1 = *p1;
        v0.x = to_tf32(v0.x); v0.y = to_tf32(v0.y); v0.z = to_tf32(v0.z); v0.w = to_tf32(v0.w);
        v1.x = to_tf32(v1.x); v1.y = to_tf32(v1.y); v1.z = to_tf32(v1.z); v1.w = to_tf32(v1.w);
        *p0 = v0; *p1 = v1;
    }
    __syncthreads();

    const int wm = warp >> 1, wn = warp & 1;
    const int group = lane >> 2, tig = lane & 3;
    const int arow0 = wm * 16 + group;
    const int brow0 = wn * 64 + group;
    const int pgrp  = ((group & 3) << 1) | (group >> 2);

    float accg[8][4], accl[8][4];
    #pragma unroll
    for (int u = 0; u < 8; ++u)
        #pragma unroll
        for (int v = 0; v < 4; ++v) { accg[u][v] = 0.0f; accl[u][v] = 0.0f; }

    #pragma unroll
    for (int ks = 0; ks < 16; ++ks) {
        const int k = ks * 8;
        uint32_t a0 = __float_as_uint(zn[arow0 * PAD + k + tig]);
        uint32_t a1 = __float_as_uint(zn[(arow0 + 8) * PAD + k + tig]);
        uint32_t a2 = __float_as_uint(zn[arow0 * PAD + k + tig + 4]);
        uint32_t a3 = __float_as_uint(zn[(arow0 + 8) * PAD + k + tig + 4]);
        #pragma unroll
        for (int u = 0; u < 8; ++u) {
            int rb = brow0 + u * 8;
            uint32_t b0 = __float_as_uint(Wt0[(k + tig) * WSTR + rb]);
            uint32_t b1 = __float_as_uint(Wt0[(k + tig + 4) * WSTR + rb]);
            mma_tf32(accg[u], a0, a1, a2, a3, b0, b1);
        }
    }
    #pragma unroll
    for (int ks = 0; ks < 16; ++ks) {
        const int k = ks * 8;
        uint32_t a0 = __float_as_uint(zn[arow0 * PAD + k + tig]);
        uint32_t a1 = __float_as_uint(zn[(arow0 + 8) * PAD + k + tig]);
        uint32_t a2 = __float_as_uint(zn[arow0 * PAD + k + tig + 4]);
        uint32_t a3 = __float_as_uint(zn[(arow0 + 8) * PAD + k + tig + 4]);
        #pragma unroll
        for (int u = 0; u < 8; ++u) {
            int rb = brow0 + u * 8;
            uint32_t b0 = __float_as_uint(Wt1[(k + tig) * WSTR + rb]);
            uint32_t b1 = __float_as_uint(Wt1[(k + tig + 4) * WSTR + rb]);
            mma_tf32(accl[u], a0, a1, a2, a3, b0, b1);
        }
    }

    const int mp = m0 + wm * 16 + pgrp;
    float* dst = g_bt + (size_t)j * LQ + mp;
    #pragma unroll
    for (int u = 0; u < 8; ++u) {
        const int col = wn * 64 + u * 8 + tig * 2;
        const float bg0 = bg[col], bg1 = bg[col + 1];
        const float bl0 = bl[col], bl1 = bl[col + 1];
        float v0 = to_tf32(sigmoidf_(accg[u][0] + bg0) * (accl[u][0] + bl0));
        float v1 = to_tf32(sigmoidf_(accg[u][1] + bg1) * (accl[u][1] + bl1));
        float v2 = to_tf32(sigmoidf_(accg[u][2] + bg0) * (accl[u][2] + bl0));
        float v3 = to_tf32(sigmoidf_(accg[u][3] + bg1) * (accl[u][3] + bl1));
        dst[(size_t)col       * LLQ]     = v0;
        dst[(size_t)(col + 1) * LLQ]     = v1;
        dst[(size_t)col       * LLQ + 8] = v2;
        dst[(size_t)(col + 1) * LLQ + 8] = v3;
    }
}

// ---------------------------------------------------------------------------
// Kernel 2: 128x256 CTA tile einsum. 512 threads = 16 warps (4m x 4n),
// warp tile 32x64 (identical to proven R11 fragment paths, EPAD 40).
// 2-stage cp.async; barriers per output halved vs 128x128.
// ---------------------------------------------------------------------------
#define EPAD 40
#define ASTG (128 * EPAD)
#define BSTG (256 * EPAD)

__global__ void __launch_bounds__(512, 1) k_einsum_cp()
{
    extern __shared__ float es[];
    float* As = es;                  // [2][ASTG]
    float* Bs = es + 2 * ASTG;       // [2][BSTG]

    const int tid  = threadIdx.x;
    const int lane = tid & 31, warp = tid >> 5;
    const int wm = warp & 3;         // 4 m-warps of 32
    const int wn = warp >> 2;        // 4 n-warps of 64
    const int c  = blockIdx.z;
    const int i0 = blockIdx.y * 128;
    const int j0 = blockIdx.x * 256;

    const float* A  = g_a  + (size_t)c * LLQ;
    const float* Bt = g_bt + (size_t)c * LLQ;

    const uint32_t sA = smem_u32(As);
    const uint32_t sB = smem_u32(Bs);

    // A: 1024 float4/stage -> 2 per thread; B: 2048 float4/stage -> 4 per thread
    int arw[2], aq[2], brw[4], bq[4];
    #pragma unroll
    for (int r = 0; r < 2; ++r) {
        int idx = r * 512 + tid;
        arw[r] = idx >> 3; aq[r] = idx & 7;
    }
    #pragma unroll
    for (int r = 0; r < 4; ++r) {
        int idx = r * 512 + tid;
        brw[r] = idx >> 3; bq[r] = idx & 7;
    }

    #pragma unroll
    for (int kt = 0; kt < 2; ++kt) {
        #pragma unroll
        for (int r = 0; r < 2; ++r) {
            uint32_t off = (uint32_t)(kt * ASTG + arw[r] * EPAD + aq[r] * 4) * 4u;
            CP_ASYNC16(sA + off, A + (size_t)(i0 + arw[r]) * LQ + kt * 32 + aq[r] * 4);
        }
        #pragma unroll
        for (int r = 0; r < 4; ++r) {
            uint32_t off = (uint32_t)(kt * BSTG + brw[r] * EPAD + bq[r] * 4) * 4u;
            CP_ASYNC16(sB + off, Bt + (size_t)(j0 + brw[r]) * LQ + kt * 32 + bq[r] * 4);
        }
        CP_COMMIT();
    }

    float acc[2][8][4];
    #pragma unroll
    for (int t = 0; t < 2; ++t)
        #pragma unroll
        for (int u = 0; u < 8; ++u)
            #pragma unroll
            for (int v = 0; v < 4; ++v) acc[t][u][v] = 0.0f;

    const int arow0 = wm * 32 + (lane >> 2);
    const int tig2  = (lane & 3) * 2;
    const int brow0 = wn * 64 + (lane >> 2);

    #pragma unroll 1
    for (int kt = 0; kt < 16; ++kt) {
        const int buf = kt & 1;
        if (kt < 14) { CP_WAIT1(); } else { CP_WAIT0(); }
        __syncthreads();

        const float* Ab = As + buf * ASTG;
        const float* Bb = Bs + buf * BSTG;

        #pragma unroll
        for (int ks = 0; ks < 4; ++ks) {
            const int fo = ks * 8 + tig2;
            uint32_t af[2][4];
            #pragma unroll
            for (int t = 0; t < 2; ++t) {
                int ra = arow0 + t * 16;
                float2 fa0 = *(const float2*)(Ab + ra * EPAD + fo);
                float2 fa1 = *(const float2*)(Ab + (ra + 8) * EPAD + fo);
                af[t][0] = __float_as_uint(fa0.x); af[t][2] = __float_as_uint(fa0.y);
                af[t][1] = __float_as_uint(fa1.x); af[t][3] = __float_as_uint(fa1.y);
            }
            #pragma unroll
            for (int u = 0; u < 8; ++u) {
                int rb = brow0 + u * 8;
                float2 fb = *(const float2*)(Bb + rb * EPAD + fo);
                uint32_t b0 = __float_as_uint(fb.x), b1 = __float_as_uint(fb.y);
                mma_tf32(acc[0][u], af[0][0], af[0][1], af[0][2], af[0][3], b0, b1);
                mma_tf32(acc[1][u], af[1][0], af[1][1], af[1][2], af[1][3], b0, b1);
            }
        }
        __syncthreads();

        if (kt + 2 < 16) {
            const int nk = kt + 2;
            #pragma unroll
            for (int r = 0; r < 2; ++r) {
                uint32_t off = (uint32_t)(buf * ASTG + arw[r] * EPAD + aq[r] * 4) * 4u;
                CP_ASYNC16(sA + off, A + (size_t)(i0 + arw[r]) * LQ + nk * 32 + aq[r] * 4);
            }
            #pragma unroll
            for (int r = 0; r < 4; ++r) {
                uint32_t off = (uint32_t)(buf * BSTG + brw[r] * EPAD + bq[r] * 4) * 4u;
                CP_ASYNC16(sB + off, Bt + (size_t)(j0 + brw[r]) * LQ + nk * 32 + bq[r] * 4);
            }
            CP_COMMIT();
        }
    }

    float* K = g_k + (size_t)c * LLQ;
    const int orow = i0 + wm * 32 + (lane >> 2);
    const int ocol = j0 + wn * 64 + (lane & 3) * 2;
    #pragma unroll
    for (int t = 0; t < 2; ++t) {
        #pragma unroll
        for (int u = 0; u < 8; ++u) {
            float* p0 = K + (size_t)(orow + t * 16)     * LQ + ocol + u * 8;
            float* p1 = K + (size_t)(orow + t * 16 + 8) * LQ + ocol + u * 8;
            *(float2*)p0 = make_float2(acc[t][u][0], acc[t][u][1]);
            *(float2*)p1 = make_float2(acc[t][u][2], acc[t][u][3]);
        }
    }
}

// ---------------------------------------------------------------------------
// Kernel 3 (R11/R9, frozen): out = sigmoid(LN(z)@Wgo+bgo) * (LN(k)@Wlo+blo)
// ---------------------------------------------------------------------------
__global__ void __launch_bounds__(512, 1) k_final(
    const float* __restrict__ z,
    const float* __restrict__ lnw, const float* __restrict__ lnb,
    const float* __restrict__ lnow, const float* __restrict__ lnob,
    const float* __restrict__ Wgo, const float* __restrict__ bgo,
    const float* __restrict__ Wlo, const float* __restrict__ blo,
    float* __restrict__ out)
{
    extern __shared__ float sm[];
    float* buf = sm;                          // [128][PAD]: zn, then kn
    float* Wt0 = sm + 128 * PAD;              // [128][WSTR]
    float* Wt1 = sm + 128 * PAD + 128 * WSTR; // [128][WSTR]

    const int tid  = threadIdx.x;
    const int r0   = blockIdx.x * 128;
    const int i    = r0 >> 9;
    const int j0   = r0 & 511;
    const int lane = tid & 31, warp = tid >> 5;

    const uint32_t sW0 = smem_u32(Wt0);
    const uint32_t sW1 = smem_u32(Wt1);
    const uint32_t sBuf = smem_u32(buf);

    #pragma unroll
    for (int it = 0; it < 8; ++it) {
        int idx = it * 512 + tid;
        int k = idx >> 5, q = idx & 31;
        uint32_t off = (uint32_t)(k * WSTR + q * 4) * 4u;
        CP_ASYNC16(sW0 + off, Wgo + k * 128 + q * 4);
        CP_ASYNC16(sW1 + off, Wlo + k * 128 + q * 4);
    }
    CP_COMMIT();

    // LN(z) -> buf
    {
        const float w0 = lnw[lane], w1 = lnw[lane + 32], w2 = lnw[lane + 64], w3 = lnw[lane + 96];
        const float c0 = lnb[lane], c1 = lnb[lane + 32], c2 = lnb[lane + 64], c3 = lnb[lane + 96];
        for (int it = 0; it < 8; ++it) {
            int row = warp * 8 + it;
            const float* zr = z + (size_t)(r0 + row) * 128;
            float x0 = zr[lane], x1 = zr[lane + 32], x2 = zr[lane + 64], x3 = zr[lane + 96];
            float s = x0 + x1 + x2 + x3;
            float q = x0 * x0 + x1 * x1 + x2 * x2 + x3 * x3;
            #pragma unroll
            for (int o = 16; o > 0; o >>= 1) {
                s += __shfl_xor_sync(0xffffffffu, s, o);
                q += __shfl_xor_sync(0xffffffffu, q, o);
            }
            float mu  = s * (1.0f / 128.0f);
            float var = q * (1.0f / 128.0f) - mu * mu;
            float rs  = rsqrtf(var + 1e-5f);
            float* zo = buf + row * PAD;
            zo[lane]      = to_tf32((x0 - mu) * rs * w0 + c0);
            zo[lane + 32] = to_tf32((x1 - mu) * rs * w1 + c1);
            zo[lane + 64] = to_tf32((x2 - mu) * rs * w2 + c2);
            zo[lane + 96] = to_tf32((x3 - mu) * rs * w3 + c3);
        }
    }

    CP_WAIT0();
    __syncthreads();
    #pragma unroll
    for (int it = 0; it < 8; ++it) {
        int idx = it * 512 + tid;
        int k = idx >> 5, q = idx & 31;
        float4* p0 = (float4*)(Wt0 + k * WSTR + q * 4);
        float4* p1 = (float4*)(Wt1 + k * WSTR + q * 4);
        float4 v0 = *p0, v1 = *p1;
        v0.x = to_tf32(v0.x); v0.y = to_tf32(v0.y); v0.z = to_tf32(v0.z); v0.w = to_tf32(v0.w);
        v1.x = to_tf32(v1.x); v1.y = to_tf32(v1.y); v1.z = to_tf32(v1.z); v1.w = to_tf32(v1.w);
        *p0 = v0; *p1 = v1;
    }
    __syncthreads();

    const int wm = warp >> 1, wn = warp & 1;
    const int group = lane >> 2, tig = lane & 3;
    const int arow0 = wm * 16 + group;
    const int brow0 = wn * 64 + group;

    float accg[8][4];
    #pragma unroll
    for (int u = 0; u < 8; ++u)
        #pragma unroll
        for (int v = 0; v < 4; ++v) accg[u][v] = 0.0f;

    #pragma unroll
    for (int ks = 0; ks < 16; ++ks) {
        const int k = ks * 8;
        uint32_t a0 = __float_as_uint(buf[arow0 * PAD + k + tig]);
        uint32_t a1 = __float_as_uint(buf[(arow0 + 8) * PAD + k + tig]);
        uint32_t a2 = __float_as_uint(buf[arow0 * PAD + k + tig + 4]);
        uint32_t a3 = __float_as_uint(buf[(arow0 + 8) * PAD + k + tig + 4]);
        #pragma unroll
        for (int u = 0; u < 8; ++u) {
            int rb = brow0 + u * 8;
            uint32_t b0 = __float_as_uint(Wt0[(k + tig) * WSTR + rb]);
            uint32_t b1 = __float_as_uint(Wt0[(k + tig + 4) * WSTR + rb]);
            mma_tf32(accg[u], a0, a1, a2, a3, b0, b1);
        }
    }
    __syncthreads();

    #pragma unroll
    for (int it = 0; it < 32; ++it) {
        int idx = it * 512 + tid;
        int jl = idx & 127;
        int c  = idx >> 7;
        CP_ASYNC4(sBuf + (uint32_t)(jl * PAD + c) * 4u,
                  g_k + (size_t)c * LLQ + (size_t)i * LQ + j0 + jl);
    }
    CP_COMMIT();
    CP_WAIT0();
    __syncthreads();

    // LN(k) in place
    {
        const float w0 = lnow[lane], w1 = lnow[lane + 32], w2 = lnow[lane + 64], w3 = lnow[lane + 96];
        const float c0 = lnob[lane], c1 = lnob[lane + 32], c2 = lnob[lane + 64], c3 = lnob[lane + 96];
        for (int it = 0; it < 8; ++it) {
            int row = warp * 8 + it;
            float* kr = buf + row * PAD;
            float x0 = kr[lane], x1 = kr[lane + 32], x2 = kr[lane + 64], x3 = kr[lane + 96];
            float s = x0 + x1 + x2 + x3;
            float q = x0 * x0 + x1 * x1 + x2 * x2 + x3 * x3;
            #pragma unroll
            for (int o = 16; o > 0; o >>= 1) {
                s += __shfl_xor_sync(0xffffffffu, s, o);
                q += __shfl_xor_sync(0xffffffffu, q, o);
            }
            float mu  = s * (1.0f / 128.0f);
            float var = q * (1.0f / 128.0f) - mu * mu;
            float rs  = rsqrtf(var + 1e-5f);
            kr[lane]      = to_tf32((x0 - mu) * rs * w0 + c0);
            kr[lane + 32] = to_tf32((x1 - mu) * rs * w1 + c1);
            kr[lane + 64] = to_tf32((x2 - mu) * rs * w2 + c2);
            kr[lane + 96] = to_tf32((x3 - mu) * rs * w3 + c3);
        }
    }
    __syncthreads();

    float accl[8][4];
    #pragma unroll
    for (int u = 0; u < 8; ++u)
        #pragma unroll
        for (int v = 0; v < 4; ++v) accl[u][v] = 0.0f;

    #pragma unroll
    for (int ks = 0; ks < 16; ++ks) {
        const int k = ks * 8;
        uint32_t a0 = __float_as_uint(buf[arow0 * PAD + k + tig]);
        uint32_t a1 = __float_as_uint(buf[(arow0 + 8) * PAD + k + tig]);
        uint32_t a2 = __float_as_uint(buf[arow0 * PAD + k + tig + 4]);
        uint32_t a3 = __float_as_uint(buf[(arow0 + 8) * PAD + k + tig + 4]);
        #pragma unroll
        for (int u = 0; u < 8; ++u) {
            int rb = brow0 + u * 8;
            uint32_t b0 = __float_as_uint(Wt1[(k + tig) * WSTR + rb]);
            uint32_t b1 = __float_as_uint(Wt1[(k + tig + 4) * WSTR + rb]);
            mma_tf32(accl[u], a0, a1, a2, a3, b0, b1);
        }
    }

    #pragma unroll
    for (int u = 0; u < 8; ++u) {
        const int col = wn * 64 + u * 8 + tig * 2;
        const float bg0 = bgo[col], bg1 = bgo[col + 1];
        const float bl0 = blo[col], bl1 = blo[col + 1];
        const int row = r0 + wm * 16 + group;
        float v0 = sigmoidf_(accg[u][0] + bg0) * (accl[u][0] + bl0);
        float v1 = sigmoidf_(accg[u][1] + bg1) * (accl[u][1] + bl1);
        float v2 = sigmoidf_(accg[u][2] + bg0) * (accl[u][2] + bl0);
        float v3 = sigmoidf_(accg[u][3] + bg1) * (accl[u][3] + bl1);
        *(float2*)(out + (size_t)row * 128 + col)       = make_float2(v0, v1);
        *(float2*)(out + (size_t)(row + 8) * 128 + col) = make_float2(v2, v3);
    }
}

// ---------------------------------------------------------------------------
extern "C" void kernel_launch(void* const* d_in, const int* in_sizes, int n_in,
                              void* d_out, int out_size)
{
    const float* z    = (const float*)d_in[0];
    const float* lnw  = (const float*)d_in[1];
    const float* lnb  = (const float*)d_in[2];
    const float* Wga  = (const float*)d_in[3];
    const float* bga  = (const float*)d_in[4];
    const float* Wla  = (const float*)d_in[5];
    const float* bla  = (const float*)d_in[6];
    const float* Wgb  = (const float*)d_in[7];
    const float* bgb  = (const float*)d_in[8];
    const float* Wlb  = (const float*)d_in[9];
    const float* blb  = (const float*)d_in[10];
    const float* lnow = (const float*)d_in[11];
    const float* lnob = (const float*)d_in[12];
    const float* Wgo  = (const float*)d_in[13];
    const float* bgo  = (const float*)d_in[14];
    const float* Wlo  = (const float*)d_in[15];
    const float* blo  = (const float*)d_in[16];
    float* out = (float*)d_out;

    const size_t smem1 = (size_t)(128 * PAD + 2 * 128 * WSTR) * sizeof(float);  // 206848
    const size_t smemE = (size_t)(2 * (ASTG + BSTG)) * sizeof(float);           // 122880
    const size_t smem3 = (size_t)(128 * PAD + 2 * 128 * WSTR) * sizeof(float);  // 206848
    cudaFuncSetAttribute(k_proj_a,    cudaFuncAttributeMaxDynamicSharedMemorySize, (int)smem1);
    cudaFuncSetAttribute(k_proj_bt,   cudaFuncAttributeMaxDynamicSharedMemorySize, (int)smem1);
    cudaFuncSetAttribute(k_einsum_cp, cudaFuncAttributeMaxDynamicSharedMemorySize, (int)smemE);
    cudaFuncSetAttribute(k_final,     cudaFuncAttributeMaxDynamicSharedMemorySize, (int)smem3);

    k_proj_a <<<2048, 512, smem1>>>(z, lnw, lnb, Wga, bga, Wla, bla);
    k_proj_bt<<<2048, 512, smem1>>>(z, lnw, lnb, Wgb, bgb, Wlb, blb);
    k_einsum_cp<<<dim3(2, 4, 128), 512, smemE>>>();
    k_final<<<2048, 512, smem3>>>(z, lnw, lnb, lnow, lnob, Wgo, bgo, Wlo, blo, out);
}

// round 16
// speedup vs baseline: 1.2240x; 1.0553x over previous
#include <cuda_runtime.h>
#include <cstdint>

#define LQ 512
#define LLQ (512*512)
#define PAD 132    // activation stride (4g+t clean)
#define WSTR 136   // weight stride (8t+g clean)

// scratch. g_a and g_bt have the K dim (m) PERMUTED within 8-blocks:
// pos = (m&~7) | ((m&3)<<1) | ((m>>2)&1)
__device__ float g_a [(size_t)128 * LLQ];   // a [c][i][perm(m)] (tf32)
__device__ float g_bt[(size_t)128 * LLQ];   // b^T [c][j][perm(m)] (tf32)
__device__ float g_k [(size_t)128 * LLQ];   // k [c][i][j]       (fp32, plain)

__device__ __forceinline__ float sigmoidf_(float x) {
    return 1.0f / (1.0f + __expf(-x));
}
__device__ __forceinline__ float to_tf32(float x) {
    uint32_t u;
    asm("cvt.rna.tf32.f32 %0, %1;" : "=r"(u) : "f"(x));
    return __uint_as_float(u);
}
__device__ __forceinline__ uint32_t smem_u32(const void* p) {
    uint32_t a;
    asm("{ .reg .u64 t; cvta.to.shared.u64 t, %1; cvt.u32.u64 %0, t; }" : "=r"(a) : "l"(p));
    return a;
}
__device__ __forceinline__ void mma_tf32(float* d, uint32_t a0, uint32_t a1, uint32_t a2, uint32_t a3,
                                         uint32_t b0, uint32_t b1) {
    asm volatile(
        "mma.sync.aligned.m16n8k8.row.col.f32.tf32.tf32.f32 "
        "{%0,%1,%2,%3}, {%4,%5,%6,%7}, {%8,%9}, {%0,%1,%2,%3};"
        : "+f"(d[0]), "+f"(d[1]), "+f"(d[2]), "+f"(d[3])
        : "r"(a0), "r"(a1), "r"(a2), "r"(a3), "r"(b0), "r"(b1));
}

#define CP_ASYNC16(dst, src) \
    asm volatile("cp.async.ca.shared.global [%0], [%1], 16;" :: "r"(dst), "l"(src) : "memory")
#define CP_ASYNC4(dst, src) \
    asm volatile("cp.async.ca.shared.global [%0], [%1], 4;"  :: "r"(dst), "l"(src) : "memory")
#define CP_COMMIT() asm volatile("cp.async.commit_group;" ::: "memory")
#define CP_WAIT1()  asm volatile("cp.async.wait_group 1;"  ::: "memory")
#define CP_WAIT0()  asm volatile("cp.async.wait_group 0;"  ::: "memory")

// batched-load LN: loads all 8 rows first (32 outstanding LDGs), then reduces.
// zr_of(it) must give the row base pointer. Results written tf32 to dstbuf
// at stride `stride`.
#define LN_BATCH8(zr_of, dstbuf, stride, W0, W1, W2, W3, C0, C1, C2, C3)        \
    do {                                                                        \
        float xs_[8][4];                                                        \
        _Pragma("unroll")                                                       \
        for (int it_ = 0; it_ < 8; ++it_) {                                     \
            const float* zr_ = (zr_of);                                         \
            xs_[it_][0] = zr_[lane];                                            \
            xs_[it_][1] = zr_[lane + 32];                                       \
            xs_[it_][2] = zr_[lane + 64];                                       \
            xs_[it_][3] = zr_[lane + 96];                                       \
        }                                                                       \
        _Pragma("unroll")                                                       \
        for (int it_ = 0; it_ < 8; ++it_) {                                     \
            int row_ = warp * 8 + it_;                                          \
            float x0 = xs_[it_][0], x1 = xs_[it_][1], x2 = xs_[it_][2], x3 = xs_[it_][3]; \
            float s_ = x0 + x1 + x2 + x3;                                       \
            float q_ = x0 * x0 + x1 * x1 + x2 * x2 + x3 * x3;                   \
            _Pragma("unroll")                                                   \
            for (int o_ = 16; o_ > 0; o_ >>= 1) {                               \
                s_ += __shfl_xor_sync(0xffffffffu, s_, o_);                     \
                q_ += __shfl_xor_sync(0xffffffffu, q_, o_);                     \
            }                                                                   \
            float mu_  = s_ * (1.0f / 128.0f);                                  \
            float var_ = q_ * (1.0f / 128.0f) - mu_ * mu_;                      \
            float rs_  = rsqrtf(var_ + 1e-5f);                                  \
            float* zo_ = (dstbuf) + row_ * (stride);                            \
            zo_[lane]      = to_tf32((x0 - mu_) * rs_ * W0 + C0);               \
            zo_[lane + 32] = to_tf32((x1 - mu_) * rs_ * W1 + C1);               \
            zo_[lane + 64] = to_tf32((x2 - mu_) * rs_ * W2 + C2);               \
            zo_[lane + 96] = to_tf32((x3 - mu_) * rs_ * W3 + C3);               \
        }                                                                       \
    } while (0)

// ---------------------------------------------------------------------------
// Kernel 1a: LN(z) + gated projection (a-pair) -> g_a [c][i][perm(m)]
// ---------------------------------------------------------------------------
__global__ void __launch_bounds__(512, 1) k_proj_a(
    const float* __restrict__ z,
    const float* __restrict__ lnw, const float* __restrict__ lnb,
    const float* __restrict__ Wg, const float* __restrict__ bg,
    const float* __restrict__ Wl, const float* __restrict__ bl)
{
    extern __shared__ float sm[];
    float* zn  = sm;                          // [128][PAD]
    float* Wt0 = sm + 128 * PAD;              // [128][WSTR]
    float* Wt1 = sm + 128 * PAD + 128 * WSTR; // [128][WSTR]

    const int tid  = threadIdx.x;
    const int r0   = blockIdx.x * 128;
    const int lane = tid & 31, warp = tid >> 5;
    const uint32_t sW0 = smem_u32(Wt0);
    const uint32_t sW1 = smem_u32(Wt1);

    #pragma unroll
    for (int it = 0; it < 8; ++it) {
        int idx = it * 512 + tid;
        int k = idx >> 5, q = idx & 31;
        uint32_t off = (uint32_t)(k * WSTR + q * 4) * 4u;
        CP_ASYNC16(sW0 + off, Wg + k * 128 + q * 4);
        CP_ASYNC16(sW1 + off, Wl + k * 128 + q * 4);
    }
    CP_COMMIT();

    {
        const float w0 = lnw[lane], w1 = lnw[lane + 32], w2 = lnw[lane + 64], w3 = lnw[lane + 96];
        const float c0 = lnb[lane], c1 = lnb[lane + 32], c2 = lnb[lane + 64], c3 = lnb[lane + 96];
        LN_BATCH8(z + (size_t)(r0 + warp * 8 + it_) * 128, zn, PAD,
                  w0, w1, w2, w3, c0, c1, c2, c3);
    }

    CP_WAIT0();
    __syncthreads();
    #pragma unroll
    for (int it = 0; it < 8; ++it) {
        int idx = it * 512 + tid;
        int k = idx >> 5, q = idx & 31;
        float4* p0 = (float4*)(Wt0 + k * WSTR + q * 4);
        float4* p1 = (float4*)(Wt1 + k * WSTR + q * 4);
        float4 v0 = *p0, v1 = *p1;
        v0.x = to_tf32(v0.x); v0.y = to_tf32(v0.y); v0.z = to_tf32(v0.z); v0.w = to_tf32(v0.w);
        v1.x = to_tf32(v1.x); v1.y = to_tf32(v1.y); v1.z = to_tf32(v1.z); v1.w = to_tf32(v1.w);
        *p0 = v0; *p1 = v1;
    }
    __syncthreads();

    const int wm = warp >> 1, wn = warp & 1;
    const int group = lane >> 2, tig = lane & 3;
    const int arow0 = wm * 16 + group;
    const int brow0 = wn * 64 + group;
    const int pgrp  = ((group & 3) << 1) | (group >> 2);

    float accg[8][4], accl[8][4];
    #pragma unroll
    for (int u = 0; u < 8; ++u)
        #pragma unroll
        for (int v = 0; v < 4; ++v) { accg[u][v] = 0.0f; accl[u][v] = 0.0f; }

    #pragma unroll
    for (int ks = 0; ks < 16; ++ks) {
        const int k = ks * 8;
        uint32_t a0 = __float_as_uint(zn[arow0 * PAD + k + tig]);
        uint32_t a1 = __float_as_uint(zn[(arow0 + 8) * PAD + k + tig]);
        uint32_t a2 = __float_as_uint(zn[arow0 * PAD + k + tig + 4]);
        uint32_t a3 = __float_as_uint(zn[(arow0 + 8) * PAD + k + tig + 4]);
        #pragma unroll
        for (int u = 0; u < 8; ++u) {
            int rb = brow0 + u * 8;
            uint32_t b0 = __float_as_uint(Wt0[(k + tig) * WSTR + rb]);
            uint32_t b1 = __float_as_uint(Wt0[(k + tig + 4) * WSTR + rb]);
            mma_tf32(accg[u], a0, a1, a2, a3, b0, b1);
        }
    }
    #pragma unroll
    for (int ks = 0; ks < 16; ++ks) {
        const int k = ks * 8;
        uint32_t a0 = __float_as_uint(zn[arow0 * PAD + k + tig]);
        uint32_t a1 = __float_as_uint(zn[(arow0 + 8) * PAD + k + tig]);
        uint32_t a2 = __float_as_uint(zn[arow0 * PAD + k + tig + 4]);
        uint32_t a3 = __float_as_uint(zn[(arow0 + 8) * PAD + k + tig + 4]);
        #pragma unroll
        for (int u = 0; u < 8; ++u) {
            int rb = brow0 + u * 8;
            uint32_t b0 = __float_as_uint(Wt1[(k + tig) * WSTR + rb]);
            uint32_t b1 = __float_as_uint(Wt1[(k + tig + 4) * WSTR + rb]);
            mma_tf32(accl[u], a0, a1, a2, a3, b0, b1);
        }
    }

    const int rowp = r0 + wm * 16 + pgrp;
    #pragma unroll
    for (int u = 0; u < 8; ++u) {
        const int col = wn * 64 + u * 8 + tig * 2;
        const float bg0 = bg[col], bg1 = bg[col + 1];
        const float bl0 = bl[col], bl1 = bl[col + 1];
        float v0 = to_tf32(sigmoidf_(accg[u][0] + bg0) * (accl[u][0] + bl0));
        float v1 = to_tf32(sigmoidf_(accg[u][1] + bg1) * (accl[u][1] + bl1));
        float v2 = to_tf32(sigmoidf_(accg[u][2] + bg0) * (accl[u][2] + bl0));
        float v3 = to_tf32(sigmoidf_(accg[u][3] + bg1) * (accl[u][3] + bl1));
        g_a[(size_t)col       * LLQ + rowp]     = v0;
        g_a[(size_t)(col + 1) * LLQ + rowp]     = v1;
        g_a[(size_t)col       * LLQ + rowp + 8] = v2;
        g_a[(size_t)(col + 1) * LLQ + rowp + 8] = v3;
    }
}

// ---------------------------------------------------------------------------
// Kernel 1b: LN(z) + gated projection (b-pair) -> g_bt [c][j][perm(m)]
// ---------------------------------------------------------------------------
__global__ void __launch_bounds__(512, 1) k_proj_bt(
    const float* __restrict__ z,
    const float* __restrict__ lnw, const float* __restrict__ lnb,
    const float* __restrict__ Wg, const float* __restrict__ bg,
    const float* __restrict__ Wl, const float* __restrict__ bl)
{
    extern __shared__ float sm[];
    float* zn  = sm;
    float* Wt0 = sm + 128 * PAD;
    float* Wt1 = sm + 128 * PAD + 128 * WSTR;

    const int tid  = threadIdx.x;
    const int m0   = (blockIdx.x & 3) * 128;
    const int j    = blockIdx.x >> 2;
    const int lane = tid & 31, warp = tid >> 5;
    const uint32_t sW0 = smem_u32(Wt0);
    const uint32_t sW1 = smem_u32(Wt1);

    #pragma unroll
    for (int it = 0; it < 8; ++it) {
        int idx = it * 512 + tid;
        int k = idx >> 5, q = idx & 31;
        uint32_t off = (uint32_t)(k * WSTR + q * 4) * 4u;
        CP_ASYNC16(sW0 + off, Wg + k * 128 + q * 4);
        CP_ASYNC16(sW1 + off, Wl + k * 128 + q * 4);
    }
    CP_COMMIT();

    {
        const float w0 = lnw[lane], w1 = lnw[lane + 32], w2 = lnw[lane + 64], w3 = lnw[lane + 96];
        const float c0 = lnb[lane], c1 = lnb[lane + 32], c2 = lnb[lane + 64], c3 = lnb[lane + 96];
        LN_BATCH8(z + ((size_t)(m0 + warp * 8 + it_) * LQ + j) * 128, zn, PAD,
                  w0, w1, w2, w3, c0, c1, c2, c3);
    }

    CP_WAIT0();
    __syncthreads();
    #pragma unroll
    for (int it = 0; it < 8; ++it) {
        int idx = it * 512 + tid;
        int k = idx >> 5, q = idx & 31;
        float4* p0 = (float4*)(Wt0 + k * WSTR + q * 4);
        float4* p1 = (float4*)(Wt1 + k * WSTR + q * 4);
        float4 v0 = *p0, v1 = *p1;
        v0.x = to_tf32(v0.x); v0.y = to_tf32(v0.y); v0.z = to_tf32(v0.z); v0.w = to_tf32(v0.w);
        v1.x = to_tf32(v1.x); v1.y = to_tf32(v1.y); v1.z = to_tf32(v1.z); v1.w = to_tf32(v1.w);
        *p0 = v0; *p1 = v1;
    }
    __syncthreads();

    const int wm = warp >> 1, wn = warp & 1;
    const int group = lane >> 2, tig = lane & 3;
    const int arow0 = wm * 16 + group;
    const int brow0 = wn * 64 + group;
    const int pgrp  = ((group & 3) << 1) | (group >> 2);

    float accg[8][4], accl[8][4];
    #pragma unroll
    for (int u = 0; u < 8; ++u)
        #pragma unroll
        for (int v = 0; v < 4; ++v) { accg[u][v] = 0.0f; accl[u][v] = 0.0f; }

    #pragma unroll
    for (int ks = 0; ks < 16; ++ks) {
        const int k = ks * 8;
        uint32_t a0 = __float_as_uint(zn[arow0 * PAD + k + tig]);
        uint32_t a1 = __float_as_uint(zn[(arow0 + 8) * PAD + k + tig]);
        uint32_t a2 = __float_as_uint(zn[arow0 * PAD + k + tig + 4]);
        uint32_t a3 = __float_as_uint(zn[(arow0 + 8) * PAD + k + tig + 4]);
        #pragma unroll
        for (int u = 0; u < 8; ++u) {
            int rb = brow0 + u * 8;
            uint32_t b0 = __float_as_uint(Wt0[(k + tig) * WSTR + rb]);
            uint32_t b1 = __float_as_uint(Wt0[(k + tig + 4) * WSTR + rb]);
            mma_tf32(accg[u], a0, a1, a2, a3, b0, b1);
        }
    }
    #pragma unroll
    for (int ks = 0; ks < 16; ++ks) {
        const int k = ks * 8;
        uint32_t a0 = __float_as_uint(zn[arow0 * PAD + k + tig]);
        uint32_t a1 = __float_as_uint(zn[(arow0 + 8) * PAD + k + tig]);
        uint32_t a2 = __float_as_uint(zn[arow0 * PAD + k + tig + 4]);
        uint32_t a3 = __float_as_uint(zn[(arow0 + 8) * PAD + k + tig + 4]);
        #pragma unroll
        for (int u = 0; u < 8; ++u) {
            int rb = brow0 + u * 8;
            uint32_t b0 = __float_as_uint(Wt1[(k + tig) * WSTR + rb]);
            uint32_t b1 = __float_as_uint(Wt1[(k + tig + 4) * WSTR + rb]);
            mma_tf32(accl[u], a0, a1, a2, a3, b0, b1);
        }
    }

    const int mp = m0 + wm * 16 + pgrp;
    float* dst = g_bt + (size_t)j * LQ + mp;
    #pragma unroll
    for (int u = 0; u < 8; ++u) {
        const int col = wn * 64 + u * 8 + tig * 2;
        const float bg0 = bg[col], bg1 = bg[col + 1];
        const float bl0 = bl[col], bl1 = bl[col + 1];
        float v0 = to_tf32(sigmoidf_(accg[u][0] + bg0) * (accl[u][0] + bl0));
        float v1 = to_tf32(sigmoidf_(accg[u][1] + bg1) * (accl[u][1] + bl1));
        float v2 = to_tf32(sigmoidf_(accg[u][2] + bg0) * (accl[u][2] + bl0));
        float v3 = to_tf32(sigmoidf_(accg[u][3] + bg1) * (accl[u][3] + bl1));
        dst[(size_t)col       * LLQ]     = v0;
        dst[(size_t)(col + 1) * LLQ]     = v1;
        dst[(size_t)col       * LLQ + 8] = v2;
        dst[(size_t)(col + 1) * LLQ + 8] = v3;
    }
}

// ---------------------------------------------------------------------------
// Kernel 2 (R11): 2-stage cp.async mma.sync TF32 einsum, permuted-K, EPAD 40.
// 256 threads, 2 CTAs/SM.
// ---------------------------------------------------------------------------
#define EPAD 40
#define ESTG (128 * EPAD)

__global__ void __launch_bounds__(256, 2) k_einsum_cp()
{
    extern __shared__ float es[];
    float* As = es;
    float* Bs = es + 2 * ESTG;

    const int tid  = threadIdx.x;
    const int lane = tid & 31, warp = tid >> 5;
    const int wm = warp & 3;
    const int wn = warp >> 2;
    const int c  = blockIdx.z;
    const int i0 = blockIdx.y * 128;
    const int j0 = blockIdx.x * 128;

    const float* A  = g_a  + (size_t)c * LLQ;
    const float* Bt = g_bt + (size_t)c * LLQ;

    const uint32_t sA = smem_u32(As);
    const uint32_t sB = smem_u32(Bs);

    int lrow[4], lq[4];
    #pragma unroll
    for (int r = 0; r < 4; ++r) {
        int idx = r * 256 + tid;
        lrow[r] = idx >> 3;
        lq[r]   = idx & 7;
    }

    #pragma unroll
    for (int kt = 0; kt < 2; ++kt) {
        #pragma unroll
        for (int r = 0; r < 4; ++r) {
            uint32_t off = (uint32_t)(kt * ESTG + lrow[r] * EPAD + lq[r] * 4) * 4u;
            CP_ASYNC16(sA + off, A  + (size_t)(i0 + lrow[r]) * LQ + kt * 32 + lq[r] * 4);
            CP_ASYNC16(sB + off, Bt + (size_t)(j0 + lrow[r]) * LQ + kt * 32 + lq[r] * 4);
        }
        CP_COMMIT();
    }

    float acc[2][8][4];
    #pragma unroll
    for (int t = 0; t < 2; ++t)
        #pragma unroll
        for (int u = 0; u < 8; ++u)
            #pragma unroll
            for (int v = 0; v < 4; ++v) acc[t][u][v] = 0.0f;

    const int arow0 = wm * 32 + (lane >> 2);
    const int tig2  = (lane & 3) * 2;
    const int brow0 = wn * 64 + (lane >> 2);

    #pragma unroll 1
    for (int kt = 0; kt < 16; ++kt) {
        const int buf = kt & 1;
        if (kt < 14) { CP_WAIT1(); } else { CP_WAIT0(); }
        __syncthreads();

        const float* Ab = As + buf * ESTG;
        const float* Bb = Bs + buf * ESTG;

        #pragma unroll
        for (int ks = 0; ks < 4; ++ks) {
            const int fo = ks * 8 + tig2;
            uint32_t af[2][4];
            #pragma unroll
            for (int t = 0; t < 2; ++t) {
                int ra = arow0 + t * 16;
                float2 fa0 = *(const float2*)(Ab + ra * EPAD + fo);
                float2 fa1 = *(const float2*)(Ab + (ra + 8) * EPAD + fo);
                af[t][0] = __float_as_uint(fa0.x); af[t][2] = __float_as_uint(fa0.y);
                af[t][1] = __float_as_uint(fa1.x); af[t][3] = __float_as_uint(fa1.y);
            }
            #pragma unroll
            for (int u = 0; u < 8; ++u) {
                int rb = brow0 + u * 8;
                float2 fb = *(const float2*)(Bb + rb * EPAD + fo);
                uint32_t b0 = __float_as_uint(fb.x), b1 = __float_as_uint(fb.y);
                mma_tf32(acc[0][u], af[0][0], af[0][1], af[0][2], af[0][3], b0, b1);
                mma_tf32(acc[1][u], af[1][0], af[1][1], af[1][2], af[1][3], b0, b1);
            }
        }
        __syncthreads();

        if (kt + 2 < 16) {
            const int nk = kt + 2;
            #pragma unroll
            for (int r = 0; r < 4; ++r) {
                uint32_t off = (uint32_t)(buf * ESTG + lrow[r] * EPAD + lq[r] * 4) * 4u;
                CP_ASYNC16(sA + off, A  + (size_t)(i0 + lrow[r]) * LQ + nk * 32 + lq[r] * 4);
                CP_ASYNC16(sB + off, Bt + (size_t)(j0 + lrow[r]) * LQ + nk * 32 + lq[r] * 4);
            }
            CP_COMMIT();
        }
    }

    float* K = g_k + (size_t)c * LLQ;
    const int orow = i0 + wm * 32 + (lane >> 2);
    const int ocol = j0 + wn * 64 + (lane & 3) * 2;
    #pragma unroll
    for (int t = 0; t < 2; ++t) {
        #pragma unroll
        for (int u = 0; u < 8; ++u) {
            float* p0 = K + (size_t)(orow + t * 16)     * LQ + ocol + u * 8;
            float* p1 = K + (size_t)(orow + t * 16 + 8) * LQ + ocol + u * 8;
            *(float2*)p0 = make_float2(acc[t][u][0], acc[t][u][1]);
            *(float2*)p1 = make_float2(acc[t][u][2], acc[t][u][3]);
        }
    }
}

// ---------------------------------------------------------------------------
// Kernel 3 (R11, frozen + batched LN(z) loads)
// ---------------------------------------------------------------------------
__global__ void __launch_bounds__(512, 1) k_final(
    const float* __restrict__ z,
    const float* __restrict__ lnw, const float* __restrict__ lnb,
    const float* __restrict__ lnow, const float* __restrict__ lnob,
    const float* __restrict__ Wgo, const float* __restrict__ bgo,
    const float* __restrict__ Wlo, const float* __restrict__ blo,
    float* __restrict__ out)
{
    extern __shared__ float sm[];
    float* buf = sm;                          // [128][PAD]: zn, then kn
    float* Wt0 = sm + 128 * PAD;              // [128][WSTR]
    float* Wt1 = sm + 128 * PAD + 128 * WSTR; // [128][WSTR]

    const int tid  = threadIdx.x;
    const int r0   = blockIdx.x * 128;
    const int i    = r0 >> 9;
    const int j0   = r0 & 511;
    const int lane = tid & 31, warp = tid >> 5;

    const uint32_t sW0 = smem_u32(Wt0);
    const uint32_t sW1 = smem_u32(Wt1);
    const uint32_t sBuf = smem_u32(buf);

    #pragma unroll
    for (int it = 0; it < 8; ++it) {
        int idx = it * 512 + tid;
        int k = idx >> 5, q = idx & 31;
        uint32_t off = (uint32_t)(k * WSTR + q * 4) * 4u;
        CP_ASYNC16(sW0 + off, Wgo + k * 128 + q * 4);
        CP_ASYNC16(sW1 + off, Wlo + k * 128 + q * 4);
    }
    CP_COMMIT();

    {
        const float w0 = lnw[lane], w1 = lnw[lane + 32], w2 = lnw[lane + 64], w3 = lnw[lane + 96];
        const float c0 = lnb[lane], c1 = lnb[lane + 32], c2 = lnb[lane + 64], c3 = lnb[lane + 96];
        LN_BATCH8(z + (size_t)(r0 + warp * 8 + it_) * 128, buf, PAD,
                  w0, w1, w2, w3, c0, c1, c2, c3);
    }

    CP_WAIT0();
    __syncthreads();
    #pragma unroll
    for (int it = 0; it < 8; ++it) {
        int idx = it * 512 + tid;
        int k = idx >> 5, q = idx & 31;
        float4* p0 = (float4*)(Wt0 + k * WSTR + q * 4);
        float4* p1 = (float4*)(Wt1 + k * WSTR + q * 4);
        float4 v0 = *p0, v1 = *p1;
        v0.x = to_tf32(v0.x); v0.y = to_tf32(v0.y); v0.z = to_tf32(v0.z); v0.w = to_tf32(v0.w);
        v1.x = to_tf32(v1.x); v1.y = to_tf32(v1.y); v1.z = to_tf32(v1.z); v1.w = to_tf32(v1.w);
        *p0 = v0; *p1 = v1;
    }
    __syncthreads();

    const int wm = warp >> 1, wn = warp & 1;
    const int group = lane >> 2, tig = lane & 3;
    const int arow0 = wm * 16 + group;
    const int brow0 = wn * 64 + group;

    float accg[8][4];
    #pragma unroll
    for (int u = 0; u < 8; ++u)
        #pragma unroll
        for (int v = 0; v < 4; ++v) accg[u][v] = 0.0f;

    #pragma unroll
    for (int ks = 0; ks < 16; ++ks) {
        const int k = ks * 8;
        uint32_t a0 = __float_as_uint(buf[arow0 * PAD + k + tig]);
        uint32_t a1 = __float_as_uint(buf[(arow0 + 8) * PAD + k + tig]);
        uint32_t a2 = __float_as_uint(buf[arow0 * PAD + k + tig + 4]);
        uint32_t a3 = __float_as_uint(buf[(arow0 + 8) * PAD + k + tig + 4]);
        #pragma unroll
        for (int u = 0; u < 8; ++u) {
            int rb = brow0 + u * 8;
            uint32_t b0 = __float_as_uint(Wt0[(k + tig) * WSTR + rb]);
            uint32_t b1 = __float_as_uint(Wt0[(k + tig + 4) * WSTR + rb]);
            mma_tf32(accg[u], a0, a1, a2, a3, b0, b1);
        }
    }
    __syncthreads();

    #pragma unroll
    for (int it = 0; it < 32; ++it) {
        int idx = it * 512 + tid;
        int jl = idx & 127;
        int c  = idx >> 7;
        CP_ASYNC4(sBuf + (uint32_t)(jl * PAD + c) * 4u,
                  g_k + (size_t)c * LLQ + (size_t)i * LQ + j0 + jl);
    }
    CP_COMMIT();
    CP_WAIT0();
    __syncthreads();

    // LN(k) in place
    {
        const float w0 = lnow[lane], w1 = lnow[lane + 32], w2 = lnow[lane + 64], w3 = lnow[lane + 96];
        const float c0 = lnob[lane], c1 = lnob[lane + 32], c2 = lnob[lane + 64], c3 = lnob[lane + 96];
        for (int it = 0; it < 8; ++it) {
            int row = warp * 8 + it;
            float* kr = buf + row * PAD;
            float x0 = kr[lane], x1 = kr[lane + 32], x2 = kr[lane + 64], x3 = kr[lane + 96];
            float s = x0 + x1 + x2 + x3;
            float q = x0 * x0 + x1 * x1 + x2 * x2 + x3 * x3;
            #pragma unroll
            for (int o = 16; o > 0; o >>= 1) {
                s += __shfl_xor_sync(0xffffffffu, s, o);
                q += __shfl_xor_sync(0xffffffffu, q, o);
            }
            float mu  = s * (1.0f / 128.0f);
            float var = q * (1.0f / 128.0f) - mu * mu;
            float rs  = rsqrtf(var + 1e-5f);
            kr[lane]      = to_tf32((x0 - mu) * rs * w0 + c0);
            kr[lane + 32] = to_tf32((x1 - mu) * rs * w1 + c1);
            kr[lane + 64] = to_tf32((x2 - mu) * rs * w2 + c2);
            kr[lane + 96] = to_tf32((x3 - mu) * rs * w3 + c3);
        }
    }
    __syncthreads();

    float accl[8][4];
    #pragma unroll
    for (int u = 0; u < 8; ++u)
        #pragma unroll
        for (int v = 0; v < 4; ++v) accl[u][v] = 0.0f;

    #pragma unroll
    for (int ks = 0; ks < 16; ++ks) {
        const int k = ks * 8;
        uint32_t a0 = __float_as_uint(buf[arow0 * PAD + k + tig]);
        uint32_t a1 = __float_as_uint(buf[(arow0 + 8) * PAD + k + tig]);
        uint32_t a2 = __float_as_uint(buf[arow0 * PAD + k + tig + 4]);
        uint32_t a3 = __float_as_uint(buf[(arow0 + 8) * PAD + k + tig + 4]);
        #pragma unroll
        for (int u = 0; u < 8; ++u) {
            int rb = brow0 + u * 8;
            uint32_t b0 = __float_as_uint(Wt1[(k + tig) * WSTR + rb]);
            uint32_t b1 = __float_as_uint(Wt1[(k + tig + 4) * WSTR + rb]);
            mma_tf32(accl[u], a0, a1, a2, a3, b0, b1);
        }
    }

    #pragma unroll
    for (int u = 0; u < 8; ++u) {
        const int col = wn * 64 + u * 8 + tig * 2;
        const float bg0 = bgo[col], bg1 = bgo[col + 1];
        const float bl0 = blo[col], bl1 = blo[col + 1];
        const int row = r0 + wm * 16 + group;
        float v0 = sigmoidf_(accg[u][0] + bg0) * (accl[u][0] + bl0);
        float v1 = sigmoidf_(accg[u][1] + bg1) * (accl[u][1] + bl1);
        float v2 = sigmoidf_(accg[u][2] + bg0) * (accl[u][2] + bl0);
        float v3 = sigmoidf_(accg[u][3] + bg1) * (accl[u][3] + bl1);
        *(float2*)(out + (size_t)row * 128 + col)       = make_float2(v0, v1);
        *(float2*)(out + (size_t)(row + 8) * 128 + col) = make_float2(v2, v3);
    }
}

// ---------------------------------------------------------------------------
extern "C" void kernel_launch(void* const* d_in, const int* in_sizes, int n_in,
                              void* d_out, int out_size)
{
    const float* z    = (const float*)d_in[0];
    const float* lnw  = (const float*)d_in[1];
    const float* lnb  = (const float*)d_in[2];
    const float* Wga  = (const float*)d_in[3];
    const float* bga  = (const float*)d_in[4];
    const float* Wla  = (const float*)d_in[5];
    const float* bla  = (const float*)d_in[6];
    const float* Wgb  = (const float*)d_in[7];
    const float* bgb  = (const float*)d_in[8];
    const float* Wlb  = (const float*)d_in[9];
    const float* blb  = (const float*)d_in[10];
    const float* lnow = (const float*)d_in[11];
    const float* lnob = (const float*)d_in[12];
    const float* Wgo  = (const float*)d_in[13];
    const float* bgo  = (const float*)d_in[14];
    const float* Wlo  = (const float*)d_in[15];
    const float* blo  = (const float*)d_in[16];
    float* out = (float*)d_out;

    const size_t smem1 = (size_t)(128 * PAD + 2 * 128 * WSTR) * sizeof(float);  // 206848
    const size_t smemE = (size_t)(4 * ESTG) * sizeof(float);                    // 81920
    const size_t smem3 = (size_t)(128 * PAD + 2 * 128 * WSTR) * sizeof(float);  // 206848
    cudaFuncSetAttribute(k_proj_a,    cudaFuncAttributeMaxDynamicSharedMemorySize, (int)smem1);
    cudaFuncSetAttribute(k_proj_bt,   cudaFuncAttributeMaxDynamicSharedMemorySize, (int)smem1);
    cudaFuncSetAttribute(k_einsum_cp, cudaFuncAttributeMaxDynamicSharedMemorySize, (int)smemE);
    cudaFuncSetAttribute(k_final,     cudaFuncAttributeMaxDynamicSharedMemorySize, (int)smem3);

    k_proj_a <<<2048, 512, smem1>>>(z, lnw, lnb, Wga, bga, Wla, bla);
    k_proj_bt<<<2048, 512, smem1>>>(z, lnw, lnb, Wgb, bgb, Wlb, blb);
    k_einsum_cp<<<dim3(4, 4, 128), 256, smemE>>>();
    k_final<<<2048, 512, smem3>>>(z, lnw, lnb, lnow, lnob, Wgo, bgo, Wlo, blo, out);
}

// round 17
// speedup vs baseline: 1.2269x; 1.0023x over previous
#include <cuda_runtime.h>
#include <cstdint>

#define LQ 512
#define LLQ (512*512)
#define PAD 132    // activation stride (4g+t clean)
#define WSTR 136   // weight stride (8t+g clean)

// scratch. g_a and g_bt have the K dim (m) PERMUTED within 8-blocks:
// pos = (m&~7) | ((m&3)<<1) | ((m>>2)&1)
__device__ float g_a [(size_t)128 * LLQ];   // a [c][i][perm(m)] (tf32)
__device__ float g_bt[(size_t)128 * LLQ];   // b^T [c][j][perm(m)] (tf32)
__device__ float g_k [(size_t)128 * LLQ];   // k [c][i][j]       (fp32, plain)

__device__ __forceinline__ float sigmoidf_(float x) {
    return 1.0f / (1.0f + __expf(-x));
}
__device__ __forceinline__ float to_tf32(float x) {
    uint32_t u;
    asm("cvt.rna.tf32.f32 %0, %1;" : "=r"(u) : "f"(x));
    return __uint_as_float(u);
}
__device__ __forceinline__ uint32_t smem_u32(const void* p) {
    uint32_t a;
    asm("{ .reg .u64 t; cvta.to.shared.u64 t, %1; cvt.u32.u64 %0, t; }" : "=r"(a) : "l"(p));
    return a;
}
__device__ __forceinline__ void mma_tf32(float* d, uint32_t a0, uint32_t a1, uint32_t a2, uint32_t a3,
                                         uint32_t b0, uint32_t b1) {
    asm volatile(
        "mma.sync.aligned.m16n8k8.row.col.f32.tf32.tf32.f32 "
        "{%0,%1,%2,%3}, {%4,%5,%6,%7}, {%8,%9}, {%0,%1,%2,%3};"
        : "+f"(d[0]), "+f"(d[1]), "+f"(d[2]), "+f"(d[3])
        : "r"(a0), "r"(a1), "r"(a2), "r"(a3), "r"(b0), "r"(b1));
}

#define CP_ASYNC16(dst, src) \
    asm volatile("cp.async.ca.shared.global [%0], [%1], 16;" :: "r"(dst), "l"(src) : "memory")
#define CP_ASYNC4(dst, src) \
    asm volatile("cp.async.ca.shared.global [%0], [%1], 4;"  :: "r"(dst), "l"(src) : "memory")
#define CP_COMMIT() asm volatile("cp.async.commit_group;" ::: "memory")
#define CP_WAIT1()  asm volatile("cp.async.wait_group 1;"  ::: "memory")
#define CP_WAIT0()  asm volatile("cp.async.wait_group 0;"  ::: "memory")

// batched-load LN: loads all 8 rows first (32 outstanding LDGs), then reduces.
#define LN_BATCH8(zr_of, dstbuf, stride, W0, W1, W2, W3, C0, C1, C2, C3)        \
    do {                                                                        \
        float xs_[8][4];                                                        \
        _Pragma("unroll")                                                       \
        for (int it_ = 0; it_ < 8; ++it_) {                                     \
            const float* zr_ = (zr_of);                                         \
            xs_[it_][0] = zr_[lane];                                            \
            xs_[it_][1] = zr_[lane + 32];                                       \
            xs_[it_][2] = zr_[lane + 64];                                       \
            xs_[it_][3] = zr_[lane + 96];                                       \
        }                                                                       \
        _Pragma("unroll")                                                       \
        for (int it_ = 0; it_ < 8; ++it_) {                                     \
            int row_ = warp * 8 + it_;                                          \
            float x0 = xs_[it_][0], x1 = xs_[it_][1], x2 = xs_[it_][2], x3 = xs_[it_][3]; \
            float s_ = x0 + x1 + x2 + x3;                                       \
            float q_ = x0 * x0 + x1 * x1 + x2 * x2 + x3 * x3;                   \
            _Pragma("unroll")                                                   \
            for (int o_ = 16; o_ > 0; o_ >>= 1) {                               \
                s_ += __shfl_xor_sync(0xffffffffu, s_, o_);                     \
                q_ += __shfl_xor_sync(0xffffffffu, q_, o_);                     \
            }                                                                   \
            float mu_  = s_ * (1.0f / 128.0f);                                  \
            float var_ = q_ * (1.0f / 128.0f) - mu_ * mu_;                      \
            float rs_  = rsqrtf(var_ + 1e-5f);                                  \
            float* zo_ = (dstbuf) + row_ * (stride);                            \
            zo_[lane]      = to_tf32((x0 - mu_) * rs_ * W0 + C0);               \
            zo_[lane + 32] = to_tf32((x1 - mu_) * rs_ * W1 + C1);               \
            zo_[lane + 64] = to_tf32((x2 - mu_) * rs_ * W2 + C2);               \
            zo_[lane + 96] = to_tf32((x3 - mu_) * rs_ * W3 + C3);               \
        }                                                                       \
    } while (0)

// ---------------------------------------------------------------------------
// Kernel 1a: LN(z) + gated projection (a-pair) -> g_a [c][i][perm(m)]
// ---------------------------------------------------------------------------
__global__ void __launch_bounds__(512, 1) k_proj_a(
    const float* __restrict__ z,
    const float* __restrict__ lnw, const float* __restrict__ lnb,
    const float* __restrict__ Wg, const float* __restrict__ bg,
    const float* __restrict__ Wl, const float* __restrict__ bl)
{
    extern __shared__ float sm[];
    float* zn  = sm;                          // [128][PAD]
    float* Wt0 = sm + 128 * PAD;              // [128][WSTR]
    float* Wt1 = sm + 128 * PAD + 128 * WSTR; // [128][WSTR]

    const int tid  = threadIdx.x;
    const int r0   = blockIdx.x * 128;
    const int lane = tid & 31, warp = tid >> 5;
    const uint32_t sW0 = smem_u32(Wt0);
    const uint32_t sW1 = smem_u32(Wt1);

    #pragma unroll
    for (int it = 0; it < 8; ++it) {
        int idx = it * 512 + tid;
        int k = idx >> 5, q = idx & 31;
        uint32_t off = (uint32_t)(k * WSTR + q * 4) * 4u;
        CP_ASYNC16(sW0 + off, Wg + k * 128 + q * 4);
        CP_ASYNC16(sW1 + off, Wl + k * 128 + q * 4);
    }
    CP_COMMIT();

    {
        const float w0 = lnw[lane], w1 = lnw[lane + 32], w2 = lnw[lane + 64], w3 = lnw[lane + 96];
        const float c0 = lnb[lane], c1 = lnb[lane + 32], c2 = lnb[lane + 64], c3 = lnb[lane + 96];
        LN_BATCH8(z + (size_t)(r0 + warp * 8 + it_) * 128, zn, PAD,
                  w0, w1, w2, w3, c0, c1, c2, c3);
    }

    CP_WAIT0();
    __syncthreads();
    #pragma unroll
    for (int it = 0; it < 8; ++it) {
        int idx = it * 512 + tid;
        int k = idx >> 5, q = idx & 31;
        float4* p0 = (float4*)(Wt0 + k * WSTR + q * 4);
        float4* p1 = (float4*)(Wt1 + k * WSTR + q * 4);
        float4 v0 = *p0, v1 = *p1;
        v0.x = to_tf32(v0.x); v0.y = to_tf32(v0.y); v0.z = to_tf32(v0.z); v0.w = to_tf32(v0.w);
        v1.x = to_tf32(v1.x); v1.y = to_tf32(v1.y); v1.z = to_tf32(v1.z); v1.w = to_tf32(v1.w);
        *p0 = v0; *p1 = v1;
    }
    __syncthreads();

    const int wm = warp >> 1, wn = warp & 1;
    const int group = lane >> 2, tig = lane & 3;
    const int arow0 = wm * 16 + group;
    const int brow0 = wn * 64 + group;
    const int pgrp  = ((group & 3) << 1) | (group >> 2);

    float accg[8][4], accl[8][4];
    #pragma unroll
    for (int u = 0; u < 8; ++u)
        #pragma unroll
        for (int v = 0; v < 4; ++v) { accg[u][v] = 0.0f; accl[u][v] = 0.0f; }

    #pragma unroll
    for (int ks = 0; ks < 16; ++ks) {
        const int k = ks * 8;
        uint32_t a0 = __float_as_uint(zn[arow0 * PAD + k + tig]);
        uint32_t a1 = __float_as_uint(zn[(arow0 + 8) * PAD + k + tig]);
        uint32_t a2 = __float_as_uint(zn[arow0 * PAD + k + tig + 4]);
        uint32_t a3 = __float_as_uint(zn[(arow0 + 8) * PAD + k + tig + 4]);
        #pragma unroll
        for (int u = 0; u < 8; ++u) {
            int rb = brow0 + u * 8;
            uint32_t b0 = __float_as_uint(Wt0[(k + tig) * WSTR + rb]);
            uint32_t b1 = __float_as_uint(Wt0[(k + tig + 4) * WSTR + rb]);
            mma_tf32(accg[u], a0, a1, a2, a3, b0, b1);
        }
    }
    #pragma unroll
    for (int ks = 0; ks < 16; ++ks) {
        const int k = ks * 8;
        uint32_t a0 = __float_as_uint(zn[arow0 * PAD + k + tig]);
        uint32_t a1 = __float_as_uint(zn[(arow0 + 8) * PAD + k + tig]);
        uint32_t a2 = __float_as_uint(zn[arow0 * PAD + k + tig + 4]);
        uint32_t a3 = __float_as_uint(zn[(arow0 + 8) * PAD + k + tig + 4]);
        #pragma unroll
        for (int u = 0; u < 8; ++u) {
            int rb = brow0 + u * 8;
            uint32_t b0 = __float_as_uint(Wt1[(k + tig) * WSTR + rb]);
            uint32_t b1 = __float_as_uint(Wt1[(k + tig + 4) * WSTR + rb]);
            mma_tf32(accl[u], a0, a1, a2, a3, b0, b1);
        }
    }

    const int rowp = r0 + wm * 16 + pgrp;
    #pragma unroll
    for (int u = 0; u < 8; ++u) {
        const int col = wn * 64 + u * 8 + tig * 2;
        const float bg0 = bg[col], bg1 = bg[col + 1];
        const float bl0 = bl[col], bl1 = bl[col + 1];
        float v0 = to_tf32(sigmoidf_(accg[u][0] + bg0) * (accl[u][0] + bl0));
        float v1 = to_tf32(sigmoidf_(accg[u][1] + bg1) * (accl[u][1] + bl1));
        float v2 = to_tf32(sigmoidf_(accg[u][2] + bg0) * (accl[u][2] + bl0));
        float v3 = to_tf32(sigmoidf_(accg[u][3] + bg1) * (accl[u][3] + bl1));
        g_a[(size_t)col       * LLQ + rowp]     = v0;
        g_a[(size_t)(col + 1) * LLQ + rowp]     = v1;
        g_a[(size_t)col       * LLQ + rowp + 8] = v2;
        g_a[(size_t)(col + 1) * LLQ + rowp + 8] = v3;
    }
}

// ---------------------------------------------------------------------------
// Kernel 1b: LN(z) + gated projection (b-pair) -> g_bt [c][j][perm(m)]
// ---------------------------------------------------------------------------
__global__ void __launch_bounds__(512, 1) k_proj_bt(
    const float* __restrict__ z,
    const float* __restrict__ lnw, const float* __restrict__ lnb,
    const float* __restrict__ Wg, const float* __restrict__ bg,
    const float* __restrict__ Wl, const float* __restrict__ bl)
{
    extern __shared__ float sm[];
    float* zn  = sm;
    float* Wt0 = sm + 128 * PAD;
    float* Wt1 = sm + 128 * PAD + 128 * WSTR;

    const int tid  = threadIdx.x;
    const int m0   = (blockIdx.x & 3) * 128;
    const int j    = blockIdx.x >> 2;
    const int lane = tid & 31, warp = tid >> 5;
    const uint32_t sW0 = smem_u32(Wt0);
    const uint32_t sW1 = smem_u32(Wt1);

    #pragma unroll
    for (int it = 0; it < 8; ++it) {
        int idx = it * 512 + tid;
        int k = idx >> 5, q = idx & 31;
        uint32_t off = (uint32_t)(k * WSTR + q * 4) * 4u;
        CP_ASYNC16(sW0 + off, Wg + k * 128 + q * 4);
        CP_ASYNC16(sW1 + off, Wl + k * 128 + q * 4);
    }
    CP_COMMIT();

    {
        const float w0 = lnw[lane], w1 = lnw[lane + 32], w2 = lnw[lane + 64], w3 = lnw[lane + 96];
        const float c0 = lnb[lane], c1 = lnb[lane + 32], c2 = lnb[lane + 64], c3 = lnb[lane + 96];
        LN_BATCH8(z + ((size_t)(m0 + warp * 8 + it_) * LQ + j) * 128, zn, PAD,
                  w0, w1, w2, w3, c0, c1, c2, c3);
    }

    CP_WAIT0();
    __syncthreads();
    #pragma unroll
    for (int it = 0; it < 8; ++it) {
        int idx = it * 512 + tid;
        int k = idx >> 5, q = idx & 31;
        float4* p0 = (float4*)(Wt0 + k * WSTR + q * 4);
        float4* p1 = (float4*)(Wt1 + k * WSTR + q * 4);
        float4 v0 = *p0, v1 = *p1;
        v0.x = to_tf32(v0.x); v0.y = to_tf32(v0.y); v0.z = to_tf32(v0.z); v0.w = to_tf32(v0.w);
        v1.x = to_tf32(v1.x); v1.y = to_tf32(v1.y); v1.z = to_tf32(v1.z); v1.w = to_tf32(v1.w);
        *p0 = v0; *p1 = v1;
    }
    __syncthreads();

    const int wm = warp >> 1, wn = warp & 1;
    const int group = lane >> 2, tig = lane & 3;
    const int arow0 = wm * 16 + group;
    const int brow0 = wn * 64 + group;
    const int pgrp  = ((group & 3) << 1) | (group >> 2);

    float accg[8][4], accl[8][4];
    #pragma unroll
    for (int u = 0; u < 8; ++u)
        #pragma unroll
        for (int v = 0; v < 4; ++v) { accg[u][v] = 0.0f; accl[u][v] = 0.0f; }

    #pragma unroll
    for (int ks = 0; ks < 16; ++ks) {
        const int k = ks * 8;
        uint32_t a0 = __float_as_uint(zn[arow0 * PAD + k + tig]);
        uint32_t a1 = __float_as_uint(zn[(arow0 + 8) * PAD + k + tig]);
        uint32_t a2 = __float_as_uint(zn[arow0 * PAD + k + tig + 4]);
        uint32_t a3 = __float_as_uint(zn[(arow0 + 8) * PAD + k + tig + 4]);
        #pragma unroll
        for (int u = 0; u < 8; ++u) {
            int rb = brow0 + u * 8;
            uint32_t b0 = __float_as_uint(Wt0[(k + tig) * WSTR + rb]);
            uint32_t b1 = __float_as_uint(Wt0[(k + tig + 4) * WSTR + rb]);
            mma_tf32(accg[u], a0, a1, a2, a3, b0, b1);
        }
    }
    #pragma unroll
    for (int ks = 0; ks < 16; ++ks) {
        const int k = ks * 8;
        uint32_t a0 = __float_as_uint(zn[arow0 * PAD + k + tig]);
        uint32_t a1 = __float_as_uint(zn[(arow0 + 8) * PAD + k + tig]);
        uint32_t a2 = __float_as_uint(zn[arow0 * PAD + k + tig + 4]);
        uint32_t a3 = __float_as_uint(zn[(arow0 + 8) * PAD + k + tig + 4]);
        #pragma unroll
        for (int u = 0; u < 8; ++u) {
            int rb = brow0 + u * 8;
            uint32_t b0 = __float_as_uint(Wt1[(k + tig) * WSTR + rb]);
            uint32_t b1 = __float_as_uint(Wt1[(k + tig + 4) * WSTR + rb]);
            mma_tf32(accl[u], a0, a1, a2, a3, b0, b1);
        }
    }

    const int mp = m0 + wm * 16 + pgrp;
    float* dst = g_bt + (size_t)j * LQ + mp;
    #pragma unroll
    for (int u = 0; u < 8; ++u) {
        const int col = wn * 64 + u * 8 + tig * 2;
        const float bg0 = bg[col], bg1 = bg[col + 1];
        const float bl0 = bl[col], bl1 = bl[col + 1];
        float v0 = to_tf32(sigmoidf_(accg[u][0] + bg0) * (accl[u][0] + bl0));
        float v1 = to_tf32(sigmoidf_(accg[u][1] + bg1) * (accl[u][1] + bl1));
        float v2 = to_tf32(sigmoidf_(accg[u][2] + bg0) * (accl[u][2] + bl0));
        float v3 = to_tf32(sigmoidf_(accg[u][3] + bg1) * (accl[u][3] + bl1));
        dst[(size_t)col       * LLQ]     = v0;
        dst[(size_t)(col + 1) * LLQ]     = v1;
        dst[(size_t)col       * LLQ + 8] = v2;
        dst[(size_t)(col + 1) * LLQ + 8] = v3;
    }
}

// ---------------------------------------------------------------------------
// Kernel 2 (R11/R16): 2-stage cp.async mma.sync TF32 einsum, permuted-K, EPAD 40.
// ---------------------------------------------------------------------------
#define EPAD 40
#define ESTG (128 * EPAD)

__global__ void __launch_bounds__(256, 2) k_einsum_cp()
{
    extern __shared__ float es[];
    float* As = es;
    float* Bs = es + 2 * ESTG;

    const int tid  = threadIdx.x;
    const int lane = tid & 31, warp = tid >> 5;
    const int wm = warp & 3;
    const int wn = warp >> 2;
    const int c  = blockIdx.z;
    const int i0 = blockIdx.y * 128;
    const int j0 = blockIdx.x * 128;

    const float* A  = g_a  + (size_t)c * LLQ;
    const float* Bt = g_bt + (size_t)c * LLQ;

    const uint32_t sA = smem_u32(As);
    const uint32_t sB = smem_u32(Bs);

    int lrow[4], lq[4];
    #pragma unroll
    for (int r = 0; r < 4; ++r) {
        int idx = r * 256 + tid;
        lrow[r] = idx >> 3;
        lq[r]   = idx & 7;
    }

    #pragma unroll
    for (int kt = 0; kt < 2; ++kt) {
        #pragma unroll
        for (int r = 0; r < 4; ++r) {
            uint32_t off = (uint32_t)(kt * ESTG + lrow[r] * EPAD + lq[r] * 4) * 4u;
            CP_ASYNC16(sA + off, A  + (size_t)(i0 + lrow[r]) * LQ + kt * 32 + lq[r] * 4);
            CP_ASYNC16(sB + off, Bt + (size_t)(j0 + lrow[r]) * LQ + kt * 32 + lq[r] * 4);
        }
        CP_COMMIT();
    }

    float acc[2][8][4];
    #pragma unroll
    for (int t = 0; t < 2; ++t)
        #pragma unroll
        for (int u = 0; u < 8; ++u)
            #pragma unroll
            for (int v = 0; v < 4; ++v) acc[t][u][v] = 0.0f;

    const int arow0 = wm * 32 + (lane >> 2);
    const int tig2  = (lane & 3) * 2;
    const int brow0 = wn * 64 + (lane >> 2);

    #pragma unroll 1
    for (int kt = 0; kt < 16; ++kt) {
        const int buf = kt & 1;
        if (kt < 14) { CP_WAIT1(); } else { CP_WAIT0(); }
        __syncthreads();

        const float* Ab = As + buf * ESTG;
        const float* Bb = Bs + buf * ESTG;

        #pragma unroll
        for (int ks = 0; ks < 4; ++ks) {
            const int fo = ks * 8 + tig2;
            uint32_t af[2][4];
            #pragma unroll
            for (int t = 0; t < 2; ++t) {
                int ra = arow0 + t * 16;
                float2 fa0 = *(const float2*)(Ab + ra * EPAD + fo);
                float2 fa1 = *(const float2*)(Ab + (ra + 8) * EPAD + fo);
                af[t][0] = __float_as_uint(fa0.x); af[t][2] = __float_as_uint(fa0.y);
                af[t][1] = __float_as_uint(fa1.x); af[t][3] = __float_as_uint(fa1.y);
            }
            #pragma unroll
            for (int u = 0; u < 8; ++u) {
                int rb = brow0 + u * 8;
                float2 fb = *(const float2*)(Bb + rb * EPAD + fo);
                uint32_t b0 = __float_as_uint(fb.x), b1 = __float_as_uint(fb.y);
                mma_tf32(acc[0][u], af[0][0], af[0][1], af[0][2], af[0][3], b0, b1);
                mma_tf32(acc[1][u], af[1][0], af[1][1], af[1][2], af[1][3], b0, b1);
            }
        }
        __syncthreads();

        if (kt + 2 < 16) {
            const int nk = kt + 2;
            #pragma unroll
            for (int r = 0; r < 4; ++r) {
                uint32_t off = (uint32_t)(buf * ESTG + lrow[r] * EPAD + lq[r] * 4) * 4u;
                CP_ASYNC16(sA + off, A  + (size_t)(i0 + lrow[r]) * LQ + nk * 32 + lq[r] * 4);
                CP_ASYNC16(sB + off, Bt + (size_t)(j0 + lrow[r]) * LQ + nk * 32 + lq[r] * 4);
            }
            CP_COMMIT();
        }
    }

    float* K = g_k + (size_t)c * LLQ;
    const int orow = i0 + wm * 32 + (lane >> 2);
    const int ocol = j0 + wn * 64 + (lane & 3) * 2;
    #pragma unroll
    for (int t = 0; t < 2; ++t) {
        #pragma unroll
        for (int u = 0; u < 8; ++u) {
            float* p0 = K + (size_t)(orow + t * 16)     * LQ + ocol + u * 8;
            float* p1 = K + (size_t)(orow + t * 16 + 8) * LQ + ocol + u * 8;
            *(float2*)p0 = make_float2(acc[t][u][0], acc[t][u][1]);
            *(float2*)p1 = make_float2(acc[t][u][2], acc[t][u][3]);
        }
    }
}

// ---------------------------------------------------------------------------
// Kernel 3: out = sigmoid(LN(z)@Wgo + bgo) * (LN(k)@Wlo + blo)
// Overlapped schedule, proven bank patterns only:
//   zn[128][PAD], kn[128][PAD] (separate), ONE weight buffer Wt[128][WSTR].
//   entry: Wgo (g0) + kn gather (g1)  -> overlap LN(z)+gate GEMM
//   after gate GEMM: Wlo (g2) -> overlaps LN(k)
// ---------------------------------------------------------------------------
__global__ void __launch_bounds__(512, 1) k_final(
    const float* __restrict__ z,
    const float* __restrict__ lnw, const float* __restrict__ lnb,
    const float* __restrict__ lnow, const float* __restrict__ lnob,
    const float* __restrict__ Wgo, const float* __restrict__ bgo,
    const float* __restrict__ Wlo, const float* __restrict__ blo,
    float* __restrict__ out)
{
    extern __shared__ float sm[];
    float* zn = sm;                     // [128][PAD]
    float* kn = sm + 128 * PAD;         // [128][PAD]
    float* Wt = sm + 2 * 128 * PAD;     // [128][WSTR]

    const int tid  = threadIdx.x;
    const int r0   = blockIdx.x * 128;
    const int i    = r0 >> 9;
    const int j0   = r0 & 511;
    const int lane = tid & 31, warp = tid >> 5;

    const uint32_t sWt = smem_u32(Wt);
    const uint32_t sKn = smem_u32(kn);

    // group0: Wgo
    #pragma unroll
    for (int it = 0; it < 8; ++it) {
        int idx = it * 512 + tid;
        int k = idx >> 5, q = idx & 31;
        CP_ASYNC16(sWt + (uint32_t)(k * WSTR + q * 4) * 4u, Wgo + k * 128 + q * 4);
    }
    CP_COMMIT();
    // group1: kn gather (row-major, proven write pattern) — overlaps LN(z)+gate GEMM
    #pragma unroll
    for (int it = 0; it < 32; ++it) {
        int idx = it * 512 + tid;
        int jl = idx & 127;
        int c  = idx >> 7;
        CP_ASYNC4(sKn + (uint32_t)(jl * PAD + c) * 4u,
                  g_k + (size_t)c * LLQ + (size_t)i * LQ + j0 + jl);
    }
    CP_COMMIT();

    // LN(z) -> zn (batched loads)
    {
        const float w0 = lnw[lane], w1 = lnw[lane + 32], w2 = lnw[lane + 64], w3 = lnw[lane + 96];
        const float c0 = lnb[lane], c1 = lnb[lane + 32], c2 = lnb[lane + 64], c3 = lnb[lane + 96];
        LN_BATCH8(z + (size_t)(r0 + warp * 8 + it_) * 128, zn, PAD,
                  w0, w1, w2, w3, c0, c1, c2, c3);
    }

    CP_WAIT1();       // group0 (Wgo) complete; gather still in flight
    __syncthreads();
    // round Wgo in place
    #pragma unroll
    for (int it = 0; it < 8; ++it) {
        int idx = it * 512 + tid;
        int k = idx >> 5, q = idx & 31;
        float4* p0 = (float4*)(Wt + k * WSTR + q * 4);
        float4 v0 = *p0;
        v0.x = to_tf32(v0.x); v0.y = to_tf32(v0.y); v0.z = to_tf32(v0.z); v0.w = to_tf32(v0.w);
        *p0 = v0;
    }
    __syncthreads();

    const int wm = warp >> 1, wn = warp & 1;
    const int group = lane >> 2, tig = lane & 3;
    const int arow0 = wm * 16 + group;
    const int brow0 = wn * 64 + group;

    // gate GEMM: zn x Wt(Wgo)
    float accg[8][4];
    #pragma unroll
    for (int u = 0; u < 8; ++u)
        #pragma unroll
        for (int v = 0; v < 4; ++v) accg[u][v] = 0.0f;

    #pragma unroll
    for (int ks = 0; ks < 16; ++ks) {
        const int k = ks * 8;
        uint32_t a0 = __float_as_uint(zn[arow0 * PAD + k + tig]);
        uint32_t a1 = __float_as_uint(zn[(arow0 + 8) * PAD + k + tig]);
        uint32_t a2 = __float_as_uint(zn[arow0 * PAD + k + tig + 4]);
        uint32_t a3 = __float_as_uint(zn[(arow0 + 8) * PAD + k + tig + 4]);
        #pragma unroll
        for (int u = 0; u < 8; ++u) {
            int rb = brow0 + u * 8;
            uint32_t b0 = __float_as_uint(Wt[(k + tig) * WSTR + rb]);
            uint32_t b1 = __float_as_uint(Wt[(k + tig + 4) * WSTR + rb]);
            mma_tf32(accg[u], a0, a1, a2, a3, b0, b1);
        }
    }
    __syncthreads();   // Wt reads done -> free for Wlo

    // group2: Wlo -> Wt (overlaps LN(k))
    #pragma unroll
    for (int it = 0; it < 8; ++it) {
        int idx = it * 512 + tid;
        int k = idx >> 5, q = idx & 31;
        CP_ASYNC16(sWt + (uint32_t)(k * WSTR + q * 4) * 4u, Wlo + k * 128 + q * 4);
    }
    CP_COMMIT();

    CP_WAIT1();        // group1 (gather) complete; group2 in flight
    __syncthreads();

    // LN(k) in place (row-major, proven pattern)
    {
        const float w0 = lnow[lane], w1 = lnow[lane + 32], w2 = lnow[lane + 64], w3 = lnow[lane + 96];
        const float c0 = lnob[lane], c1 = lnob[lane + 32], c2 = lnob[lane + 64], c3 = lnob[lane + 96];
        for (int it = 0; it < 8; ++it) {
            int row = warp * 8 + it;
            float* kr = kn + row * PAD;
            float x0 = kr[lane], x1 = kr[lane + 32], x2 = kr[lane + 64], x3 = kr[lane + 96];
            float s = x0 + x1 + x2 + x3;
            float q = x0 * x0 + x1 * x1 + x2 * x2 + x3 * x3;
            #pragma unroll
            for (int o = 16; o > 0; o >>= 1) {
                s += __shfl_xor_sync(0xffffffffu, s, o);
                q += __shfl_xor_sync(0xffffffffu, q, o);
            }
            float mu  = s * (1.0f / 128.0f);
            float var = q * (1.0f / 128.0f) - mu * mu;
            float rs  = rsqrtf(var + 1e-5f);
            kr[lane]      = to_tf32((x0 - mu) * rs * w0 + c0);
            kr[lane + 32] = to_tf32((x1 - mu) * rs * w1 + c1);
            kr[lane + 64] = to_tf32((x2 - mu) * rs * w2 + c2);
            kr[lane + 96] = to_tf32((x3 - mu) * rs * w3 + c3);
        }
    }

    CP_WAIT0();        // group2 (Wlo) complete
    // round Wlo (each thread rounds exactly what it copied; no sync needed first)
    #pragma unroll
    for (int it = 0; it < 8; ++it) {
        int idx = it * 512 + tid;
        int k = idx >> 5, q = idx & 31;
        float4* p0 = (float4*)(Wt + k * WSTR + q * 4);
        float4 v0 = *p0;
        v0.x = to_tf32(v0.x); v0.y = to_tf32(v0.y); v0.z = to_tf32(v0.z); v0.w = to_tf32(v0.w);
        *p0 = v0;
    }
    __syncthreads();   // kn LN writes + Wt rounding visible to all

    // linear GEMM: kn x Wt(Wlo)
    float accl[8][4];
    #pragma unroll
    for (int u = 0; u < 8; ++u)
        #pragma unroll
        for (int v = 0; v < 4; ++v) accl[u][v] = 0.0f;

    #pragma unroll
    for (int ks = 0; ks < 16; ++ks) {
        const int k = ks * 8;
        uint32_t a0 = __float_as_uint(kn[arow0 * PAD + k + tig]);
        uint32_t a1 = __float_as_uint(kn[(arow0 + 8) * PAD + k + tig]);
        uint32_t a2 = __float_as_uint(kn[arow0 * PAD + k + tig + 4]);
        uint32_t a3 = __float_as_uint(kn[(arow0 + 8) * PAD + k + tig + 4]);
        #pragma unroll
        for (int u = 0; u < 8; ++u) {
            int rb = brow0 + u * 8;
            uint32_t b0 = __float_as_uint(Wt[(k + tig) * WSTR + rb]);
            uint32_t b1 = __float_as_uint(Wt[(k + tig + 4) * WSTR + rb]);
            mma_tf32(accl[u], a0, a1, a2, a3, b0, b1);
        }
    }

    #pragma unroll
    for (int u = 0; u < 8; ++u) {
        const int col = wn * 64 + u * 8 + tig * 2;
        const float bg0 = bgo[col], bg1 = bgo[col + 1];
        const float bl0 = blo[col], bl1 = blo[col + 1];
        const int row = r0 + wm * 16 + group;
        float v0 = sigmoidf_(accg[u][0] + bg0) * (accl[u][0] + bl0);
        float v1 = sigmoidf_(accg[u][1] + bg1) * (accl[u][1] + bl1);
        float v2 = sigmoidf_(accg[u][2] + bg0) * (accl[u][2] + bl0);
        float v3 = sigmoidf_(accg[u][3] + bg1) * (accl[u][3] + bl1);
        *(float2*)(out + (size_t)row * 128 + col)       = make_float2(v0, v1);
        *(float2*)(out + (size_t)(row + 8) * 128 + col) = make_float2(v2, v3);
    }
}

// ---------------------------------------------------------------------------
extern "C" void kernel_launch(void* const* d_in, const int* in_sizes, int n_in,
                              void* d_out, int out_size)
{
    const float* z    = (const float*)d_in[0];
    const float* lnw  = (const float*)d_in[1];
    const float* lnb  = (const float*)d_in[2];
    const float* Wga  = (const float*)d_in[3];
    const float* bga  = (const float*)d_in[4];
    const float* Wla  = (const float*)d_in[5];
    const float* bla  = (const float*)d_in[6];
    const float* Wgb  = (const float*)d_in[7];
    const float* bgb  = (const float*)d_in[8];
    const float* Wlb  = (const float*)d_in[9];
    const float* blb  = (const float*)d_in[10];
    const float* lnow = (const float*)d_in[11];
    const float* lnob = (const float*)d_in[12];
    const float* Wgo  = (const float*)d_in[13];
    const float* bgo  = (const float*)d_in[14];
    const float* Wlo  = (const float*)d_in[15];
    const float* blo  = (const float*)d_in[16];
    float* out = (float*)d_out;

    const size_t smem1 = (size_t)(128 * PAD + 2 * 128 * WSTR) * sizeof(float);  // 206848
    const size_t smemE = (size_t)(4 * ESTG) * sizeof(float);                    // 81920
    const size_t smem3 = (size_t)(2 * 128 * PAD + 128 * WSTR) * sizeof(float);  // 204800
    cudaFuncSetAttribute(k_proj_a,    cudaFuncAttributeMaxDynamicSharedMemorySize, (int)smem1);
    cudaFuncSetAttribute(k_proj_bt,   cudaFuncAttributeMaxDynamicSharedMemorySize, (int)smem1);
    cudaFuncSetAttribute(k_einsum_cp, cudaFuncAttributeMaxDynamicSharedMemorySize, (int)smemE);
    cudaFuncSetAttribute(k_final,     cudaFuncAttributeMaxDynamicSharedMemorySize, (int)smem3);

    k_proj_a <<<2048, 512, smem1>>>(z, lnw, lnb, Wga, bga, Wla, bla);
    k_proj_bt<<<2048, 512, smem1>>>(z, lnw, lnb, Wgb, bgb, Wlb, blb);
    k_einsum_cp<<<dim3(4, 4, 128), 256, smemE>>>();
    k_final<<<2048, 512, smem3>>>(z, lnw, lnb, lnow, lnob, Wgo, bgo, Wlo, blo, out);
}